// round 10
// baseline (speedup 1.0000x reference)
#include <cuda_runtime.h>
#include <cuda_bf16.h>
#include <math.h>
#include <stdint.h>

// ---------------------------------------------------------------------------
// Problem dims
// ---------------------------------------------------------------------------
namespace {
constexpr int B_   = 16;
constexpr int L_   = 512;
constexpr int N_   = 321;
constexpr int MK_  = 4;
constexpr int D_   = 512;
constexpr int S_   = 16;
constexpr int DTR_ = 32;
constexpr int PRED_= 96;
constexpr int T_   = N_ + MK_;        // 325
constexpr int MROWS = B_ * T_;        // 5200
constexpr int NC_  = 13;              // scan chunks
constexpr int CH_  = 25;              // steps per chunk
}

// ---------------------------------------------------------------------------
// fp32 scratch (scan / epilogue inputs)
// ---------------------------------------------------------------------------
__device__ float g_mean[B_ * N_];
__device__ float g_istd[B_ * N_];
__device__ float g_std [B_ * N_];
__device__ float g_enc  [(size_t)MROWS * D_];
__device__ float g_xz   [(size_t)MROWS * 128];
__device__ float g_dtcat[(size_t)MROWS * 1024];
__device__ float g_ycat [(size_t)MROWS * 2 * D_];
__device__ float g_hbuf [(size_t)MROWS * D_];
__device__ float g_pre  [(size_t)MROWS * PRED_];

// bf16 (hi,lo) packed-pair planes: u32 = 2 consecutive-K bf16.
// A-operand planes: [M][K/2]
__device__ uint32_t g_tokH [(size_t)MROWS * 256],  g_tokL [(size_t)MROWS * 256];
__device__ uint32_t g_encH [(size_t)MROWS * 256],  g_encL [(size_t)MROWS * 256];
__device__ uint32_t g_xzH  [(size_t)MROWS * 64],   g_xzL  [(size_t)MROWS * 64];
__device__ uint32_t g_ycatH[(size_t)MROWS * 512],  g_ycatL[(size_t)MROWS * 512];
__device__ uint32_t g_fusH [(size_t)MROWS * 256],  g_fusL [(size_t)MROWS * 256];
__device__ uint32_t g_hnH  [(size_t)MROWS * 256],  g_hnL  [(size_t)MROWS * 256];

// B-operand planes (weights, transposed to [N][K/2])
__device__ uint32_t g_wembH[512 * 256],  g_wembL[512 * 256];
__device__ uint32_t g_wxH  [128 * 256],  g_wxL  [128 * 256];
__device__ uint32_t g_wdtH [1024 * 64],  g_wdtL [1024 * 64];
__device__ uint32_t g_wzH  [512 * 512],  g_wzL  [512 * 512];
__device__ uint32_t g_woH  [512 * 256],  g_woL  [512 * 256];
__device__ uint32_t g_wpjH [96 * 256],   g_wpjL [96 * 256];
__device__ float    g_bdt  [1024];

// chunked-scan intermediates
__device__ float g_dts [2 * NC_ * B_ * D_];
__device__ float g_hfin[(size_t)2 * NC_ * B_ * S_ * D_];
__device__ float g_h0  [(size_t)2 * NC_ * B_ * S_ * D_];

// ---------------------------------------------------------------------------
// bf16 split helpers
// ---------------------------------------------------------------------------
__device__ __forceinline__ void bf16_split_pair(float x0, float x1,
                                                uint32_t& hi, uint32_t& lo)
{
    __nv_bfloat16 h0 = __float2bfloat16(x0);
    __nv_bfloat16 h1 = __float2bfloat16(x1);
    __nv_bfloat16 l0 = __float2bfloat16(x0 - __bfloat162float(h0));
    __nv_bfloat16 l1 = __float2bfloat16(x1 - __bfloat162float(h1));
    __nv_bfloat162 hp, lp;
    hp.x = h0; hp.y = h1;
    lp.x = l0; lp.y = l1;
    hi = *reinterpret_cast<uint32_t*>(&hp);
    lo = *reinterpret_cast<uint32_t*>(&lp);
}

// ---------------------------------------------------------------------------
// 0) weight split: W[K][N] row-major -> planes [N][K/2] u32 (bf16 pairs)
// ---------------------------------------------------------------------------
namespace {
constexpr int I_EMB = 512 * 256;
constexpr int I_WX  = 128 * 256;
constexpr int I_WDT = 1024 * 64;
constexpr int I_WZ  = 512 * 512;
constexpr int I_WO  = 512 * 256;
constexpr int I_WPJ = 96 * 256;
constexpr int I_ALL = I_EMB + I_WX + I_WDT + I_WZ + I_WO + I_WPJ + 1024;
}

__global__ void split_weights(const float* __restrict__ Wemb,
                              const float* __restrict__ Wxf,  const float* __restrict__ Wxb,
                              const float* __restrict__ Wdtf, const float* __restrict__ Wdtb,
                              const float* __restrict__ Wz,   const float* __restrict__ Wo,
                              const float* __restrict__ Wproj,
                              const float* __restrict__ bdtf, const float* __restrict__ bdtb)
{
    int i = blockIdx.x * 256 + threadIdx.x;
    if (i < I_EMB) {
        int n = i >> 8, kp = i & 255;
        float v0 = Wemb[(2 * kp    ) * 512 + n];
        float v1 = Wemb[(2 * kp + 1) * 512 + n];
        bf16_split_pair(v0, v1, g_wembH[i], g_wembL[i]);
        return;
    }
    i -= I_EMB;
    if (i < I_WX) {
        int n = i >> 8, kp = i & 255;
        float v0, v1;
        if (n < 64) { v0 = Wxf[(2*kp)*64 + n];       v1 = Wxf[(2*kp+1)*64 + n]; }
        else        { v0 = Wxb[(2*kp)*64 + n - 64];  v1 = Wxb[(2*kp+1)*64 + n - 64]; }
        bf16_split_pair(v0, v1, g_wxH[i], g_wxL[i]);
        return;
    }
    i -= I_WX;
    if (i < I_WDT) {
        int n = i >> 6, kp = i & 63;
        int k0 = 2 * kp, k1 = k0 + 1;
        float v0 = 0.f, v1 = 0.f;
        if (n < 512) {
            if (k0 < 32) v0 = Wdtf[k0 * 512 + n];
            if (k1 < 32) v1 = Wdtf[k1 * 512 + n];
        } else {
            if (k0 >= 64 && k0 < 96) v0 = Wdtb[(k0 - 64) * 512 + n - 512];
            if (k1 >= 64 && k1 < 96) v1 = Wdtb[(k1 - 64) * 512 + n - 512];
        }
        bf16_split_pair(v0, v1, g_wdtH[i], g_wdtL[i]);
        return;
    }
    i -= I_WDT;
    if (i < I_WZ) {
        int n = i >> 9, kp = i & 511;
        float v0 = Wz[(2 * kp    ) * 512 + n];
        float v1 = Wz[(2 * kp + 1) * 512 + n];
        bf16_split_pair(v0, v1, g_wzH[i], g_wzL[i]);
        return;
    }
    i -= I_WZ;
    if (i < I_WO) {
        int n = i >> 8, kp = i & 255;
        float v0 = Wo[(2 * kp    ) * 512 + n];
        float v1 = Wo[(2 * kp + 1) * 512 + n];
        bf16_split_pair(v0, v1, g_woH[i], g_woL[i]);
        return;
    }
    i -= I_WO;
    if (i < I_WPJ) {
        int n = i >> 8, kp = i & 255;
        float v0 = Wproj[(2 * kp    ) * PRED_ + n];
        float v1 = Wproj[(2 * kp + 1) * PRED_ + n];
        bf16_split_pair(v0, v1, g_wpjH[i], g_wpjL[i]);
        return;
    }
    i -= I_WPJ;
    if (i < 1024) g_bdt[i] = (i < 512) ? bdtf[i] : bdtb[i - 512];
}

// ---------------------------------------------------------------------------
// 1) per-(b,n) mean / std over L
// ---------------------------------------------------------------------------
__global__ void stats_kernel(const float* __restrict__ x)
{
    __shared__ float sh1[8][32];
    __shared__ float sh2[8][32];
    const int b  = blockIdx.x;
    const int tx = threadIdx.x & 31;
    const int lg = threadIdx.x >> 5;
    const int n  = blockIdx.y * 32 + tx;

    float s = 0.f, s2 = 0.f;
    if (n < N_) {
        #pragma unroll 4
        for (int l = lg; l < L_; l += 8) {
            float v = x[((size_t)b * L_ + l) * N_ + n];
            s  += v;
            s2 += v * v;
        }
    }
    sh1[lg][tx] = s;
    sh2[lg][tx] = s2;
    __syncthreads();
    if (lg == 0 && n < N_) {
        float S1 = 0.f, S2 = 0.f;
        #pragma unroll
        for (int r = 0; r < 8; r++) { S1 += sh1[r][tx]; S2 += sh2[r][tx]; }
        float mu  = S1 / (float)L_;
        float var = S2 / (float)L_ - mu * mu;
        float sd  = sqrtf(var + 1e-5f);
        g_mean[b * N_ + n] = mu;
        g_std [b * N_ + n] = sd;
        g_istd[b * N_ + n] = 1.f / sd;
    }
}

// ---------------------------------------------------------------------------
// 2) tok build -> bf16 split pair planes [MROWS][256]
// ---------------------------------------------------------------------------
__global__ void build_tok(const float* __restrict__ xe, const float* __restrict__ xm)
{
    __shared__ float tile[32][33];
    const int b  = blockIdx.z;
    const int tx = threadIdx.x, ty = threadIdx.y;
    const int t0 = blockIdx.x * 32;
    const int l0 = blockIdx.y * 32;
    const int tid = ty * 32 + tx;

    #pragma unroll
    for (int j = 0; j < 4; j++) {
        int l = l0 + ty + 8 * j;
        int t = t0 + tx;
        float v = 0.f;
        if (t < T_) {
            if (t < N_) v = (xe[((size_t)b * L_ + l) * N_ + t] - g_mean[b * N_ + t]) * g_istd[b * N_ + t];
            else        v = xm[((size_t)b * L_ + l) * MK_ + (t - N_)];
        }
        tile[ty + 8 * j][tx] = v;
    }
    __syncthreads();
    #pragma unroll
    for (int it = 0; it < 2; it++) {
        int item = tid + it * 256;
        int tl = item & 31;
        int lp = item >> 5;
        int t  = t0 + tl;
        if (t < T_) {
            float v0 = tile[2 * lp    ][tl];
            float v1 = tile[2 * lp + 1][tl];
            size_t o = ((size_t)b * T_ + t) * 256 + (l0 >> 1) + lp;
            bf16_split_pair(v0, v1, g_tokH[o], g_tokL[o]);
        }
    }
}

// ---------------------------------------------------------------------------
// mma / cp.async helpers
// ---------------------------------------------------------------------------
__device__ __forceinline__ void mma_bf16(float* c, const uint32_t* a,
                                         uint32_t b0, uint32_t b1)
{
    asm volatile(
        "mma.sync.aligned.m16n8k16.row.col.f32.bf16.bf16.f32 "
        "{%0,%1,%2,%3},{%4,%5,%6,%7},{%8,%9},{%0,%1,%2,%3};\n"
        : "+f"(c[0]), "+f"(c[1]), "+f"(c[2]), "+f"(c[3])
        : "r"(a[0]), "r"(a[1]), "r"(a[2]), "r"(a[3]), "r"(b0), "r"(b1));
}

__device__ __forceinline__ void cp_async16(void* smem_dst, const void* gsrc, int src_bytes)
{
    uint32_t saddr = (uint32_t)__cvta_generic_to_shared(smem_dst);
    asm volatile("cp.async.cg.shared.global [%0], [%1], 16, %2;\n"
                 :: "r"(saddr), "l"(gsrc), "r"(src_bytes));
}
__device__ __forceinline__ void cp_commit() { asm volatile("cp.async.commit_group;\n"); }
template<int NN>
__device__ __forceinline__ void cp_wait() { asm volatile("cp.async.wait_group %0;\n" :: "n"(NN)); }

// ---------------------------------------------------------------------------
// bf16x3 tensor-core GEMM, 3-stage cp.async pipeline, ONE sync per k-tile.
// BM=64 BN=128 BK=32, 256 threads (8 warps, 2x4 grid, 32x32 warp tiles).
// Stage: A 2 planes 64x20 u32 + B 2 planes 128x20 u32 = 30720 B; 3 stages.
// ---------------------------------------------------------------------------
constexpr int EPI_NONE = 0, EPI_SOFTPLUS = 1, EPI_SIGFUSE = 2, EPI_ADD = 3;
constexpr int LDK  = 20;
constexpr int A_PL = 64 * LDK;
constexpr int B_PL = 128 * LDK;
constexpr int STG_U = 2 * A_PL + 2 * B_PL;                    // 7680 u32
constexpr int STAGES = 3;
constexpr int GEMM_SMEM = STAGES * STG_U * (int)sizeof(uint32_t);  // 92160 B

template<int EPI>
__global__ void __launch_bounds__(256, 2)
gemm_bf(const uint32_t* __restrict__ Ahi, const uint32_t* __restrict__ Alo, int ldaU,
        const uint32_t* __restrict__ Bhi, const uint32_t* __restrict__ Blo, int ldbU,
        float* __restrict__ C, int ldc,
        uint32_t* __restrict__ CHi, uint32_t* __restrict__ CLo, int ldcU,
        int M, int Ncols, int K,
        const float* __restrict__ bias,
        const float* __restrict__ e1,
        const float* __restrict__ e2,
        int elds)
{
    constexpr int BM = 64, BN = 128, BK = 32;
    extern __shared__ uint32_t smu[];

    const int tid = threadIdx.x;
    const int w   = tid >> 5, l = tid & 31;
    const int g   = l >> 2, tg = l & 3;
    const int wr  = w >> 2, wc = w & 3;
    const int m0w = wr * 32, n0w = wc * 32;
    const int rowBase = blockIdx.y * BM;
    const int colBase = blockIdx.x * BN;

    float acc[2][4][4];
    #pragma unroll
    for (int mi = 0; mi < 2; mi++)
        #pragma unroll
        for (int ni = 0; ni < 4; ni++)
            #pragma unroll
            for (int q = 0; q < 4; q++) acc[mi][ni][q] = 0.f;

    const int KT = K / BK;

    auto load_tile = [&](int kt, int stage) {
        uint32_t* sA = smu + stage * STG_U;
        uint32_t* sB = sA + 2 * A_PL;
        const int kp0 = kt * (BK / 2);
        #pragma unroll
        for (int j = 0; j < 2; j++) {
            int idx = tid + j * 256;
            int c   = idx & 3;
            int row = (idx >> 2) & 63;
            int pl  = idx >> 8;
            int gr  = rowBase + row;
            int sz  = (gr < M) ? 16 : 0;
            int grc = (gr < M) ? gr : 0;
            const uint32_t* src = (pl ? Alo : Ahi) + (size_t)grc * ldaU + kp0 + c * 4;
            cp_async16(sA + pl * A_PL + row * LDK + c * 4, src, sz);
        }
        #pragma unroll
        for (int j = 0; j < 4; j++) {
            int idx = tid + j * 256;
            int c   = idx & 3;
            int n   = (idx >> 2) & 127;
            int pl  = idx >> 9;
            int gn  = colBase + n;
            int sz  = (gn < Ncols) ? 16 : 0;
            int gnc = (gn < Ncols) ? gn : 0;
            const uint32_t* src = (pl ? Blo : Bhi) + (size_t)gnc * ldbU + kp0 + c * 4;
            cp_async16(sB + pl * B_PL + n * LDK + c * 4, src, sz);
        }
    };

    // prologue: stages 0..STAGES-2
    load_tile(0, 0);
    cp_commit();
    if (KT > 1) load_tile(1, 1);
    cp_commit();

    for (int kt = 0; kt < KT; kt++) {
        // tile kt is group #kt; commits so far = 2 + kt(prior iters) -> allow 1 outstanding
        cp_wait<STAGES - 2>();
        __syncthreads();

        // issue next load FIRST (into stage consumed at kt-1; safe after sync)
        const int knext = kt + STAGES - 1;
        if (knext < KT) load_tile(knext, knext % STAGES);
        cp_commit();

        const uint32_t* sAh = smu + (kt % STAGES) * STG_U;
        const uint32_t* sAl = sAh + A_PL;
        const uint32_t* sBh = sAh + 2 * A_PL;
        const uint32_t* sBl = sBh + B_PL;

        #pragma unroll
        for (int ks = 0; ks < 2; ks++) {
            const int kb = ks * 8;
            uint32_t ah[2][4], al[2][4];
            #pragma unroll
            for (int mi = 0; mi < 2; mi++) {
                const int r0 = m0w + mi * 16 + g;
                ah[mi][0] = sAh[(r0    ) * LDK + kb + tg    ];
                ah[mi][1] = sAh[(r0 + 8) * LDK + kb + tg    ];
                ah[mi][2] = sAh[(r0    ) * LDK + kb + tg + 4];
                ah[mi][3] = sAh[(r0 + 8) * LDK + kb + tg + 4];
                al[mi][0] = sAl[(r0    ) * LDK + kb + tg    ];
                al[mi][1] = sAl[(r0 + 8) * LDK + kb + tg    ];
                al[mi][2] = sAl[(r0    ) * LDK + kb + tg + 4];
                al[mi][3] = sAl[(r0 + 8) * LDK + kb + tg + 4];
            }
            #pragma unroll
            for (int ni = 0; ni < 4; ni++) {
                const int n = n0w + ni * 8 + g;
                uint32_t bh0 = sBh[n * LDK + kb + tg    ];
                uint32_t bh1 = sBh[n * LDK + kb + tg + 4];
                uint32_t bl0 = sBl[n * LDK + kb + tg    ];
                uint32_t bl1 = sBl[n * LDK + kb + tg + 4];
                #pragma unroll
                for (int mi = 0; mi < 2; mi++) {
                    mma_bf16(acc[mi][ni], ah[mi], bl0, bl1);
                    mma_bf16(acc[mi][ni], al[mi], bh0, bh1);
                    mma_bf16(acc[mi][ni], ah[mi], bh0, bh1);
                }
            }
        }
    }

    // epilogue
    #pragma unroll
    for (int mi = 0; mi < 2; mi++) {
        #pragma unroll
        for (int half = 0; half < 2; half++) {
            int gr = rowBase + m0w + mi * 16 + g + half * 8;
            if (gr >= M) continue;
            #pragma unroll
            for (int ni = 0; ni < 4; ni++) {
                int gc = colBase + n0w + ni * 8 + 2 * tg;
                if (gc >= Ncols) continue;
                float x0 = acc[mi][ni][half * 2 + 0];
                float x1 = acc[mi][ni][half * 2 + 1];
                if (bias) { x0 += bias[gc]; x1 += bias[gc + 1]; }
                if (EPI == EPI_SOFTPLUS) {
                    x0 = (x0 > 15.f) ? x0 : log1pf(__expf(x0));
                    x1 = (x1 > 15.f) ? x1 : log1pf(__expf(x1));
                } else if (EPI == EPI_SIGFUSE) {
                    size_t ei = (size_t)gr * elds + gc;
                    float z0 = 1.f / (1.f + __expf(-x0));
                    float z1 = 1.f / (1.f + __expf(-x1));
                    x0 = z0 * e1[ei]     + (1.f - z0) * e2[ei];
                    x1 = z1 * e1[ei + 1] + (1.f - z1) * e2[ei + 1];
                } else if (EPI == EPI_ADD) {
                    size_t ei = (size_t)gr * elds + gc;
                    x0 += e1[ei];
                    x1 += e1[ei + 1];
                }
                if (C) {
                    C[(size_t)gr * ldc + gc]     = x0;
                    C[(size_t)gr * ldc + gc + 1] = x1;
                }
                if (CHi) {
                    size_t o = (size_t)gr * ldcU + (gc >> 1);
                    bf16_split_pair(x0, x1, CHi[o], CLo[o]);
                }
            }
        }
    }
}

// ---------------------------------------------------------------------------
// scan helpers
// ---------------------------------------------------------------------------
__device__ __forceinline__ void load_a(const float* __restrict__ AL, int d,
                                       float* a, float& a0, bool& structured)
{
    #pragma unroll
    for (int s = 0; s < S_; s++) a[s] = -expf(AL[d * S_ + s]);
    a0 = a[0];
    structured = true;
    #pragma unroll
    for (int s = 0; s < S_; s++) {
        float ideal = (float)(s + 1) * a0;
        if (fabsf(a[s] - ideal) > 1e-4f * fabsf(a[s])) structured = false;
    }
}

__device__ __forceinline__ void make_powers(float q, float* P)
{
    float q2 = q * q, q4 = q2 * q2, q8 = q4 * q4;
    P[0] = q;        P[1] = q2;       P[2] = q2 * q;    P[3] = q4;
    P[4] = q4 * q;   P[5] = q4 * q2;  P[6] = q4 * P[2]; P[7] = q8;
    P[8] = q8 * q;   P[9] = q8 * q2;  P[10]= q8 * P[2]; P[11]= q8 * q4;
    P[12]= q8 * P[4];P[13]= q8 * P[5];P[14]= q8 * P[6]; P[15]= q8 * q8;
}

__device__ __forceinline__ void calc_P(bool structured, float a0, const float* a,
                                       float x, float* P)
{
    if (structured) {
        make_powers(__expf(a0 * x), P);
    } else {
        #pragma unroll
        for (int s = 0; s < 16; s++) P[s] = __expf(a[s] * x);
    }
}

// Phase A
__global__ void __launch_bounds__(128)
scan_partial(const float* __restrict__ Alogf, const float* __restrict__ Alogb)
{
    const int bx  = blockIdx.x;
    const int db  = bx & 3;
    const int c   = bx >> 2;
    const int d   = db * 128 + threadIdx.x;
    const int b   = blockIdx.y;
    const int dir = blockIdx.z;

    float a[S_], a0; bool structured;
    load_a(dir ? Alogb : Alogf, d, a, a0, structured);

    float h[S_];
    #pragma unroll
    for (int s = 0; s < S_; s++) h[s] = 0.f;
    float dts = 0.f;

    for (int t = c * CH_; t < c * CH_ + CH_; t++) {
        const int tt = dir ? (T_ - 1 - t) : t;
        const size_t rb = (size_t)b * T_ + tt;
        const float dtv = g_dtcat[rb * 1024 + dir * 512 + d];
        const float u   = g_enc[rb * D_ + d];
        const float du  = dtv * u;
        dts += dtv;

        const float4* v4 = reinterpret_cast<const float4*>(g_xz + rb * 128 + dir * 64 + 32);
        float4 B0 = v4[0], B1 = v4[1], B2 = v4[2], B3 = v4[3];
        float bc[16] = {B0.x,B0.y,B0.z,B0.w, B1.x,B1.y,B1.z,B1.w,
                        B2.x,B2.y,B2.z,B2.w, B3.x,B3.y,B3.z,B3.w};

        float P[16];
        calc_P(structured, a0, a, dtv, P);

        #pragma unroll
        for (int s = 0; s < 16; s++) h[s] = fmaf(P[s], h[s], du * bc[s]);
    }

    const size_t base = (size_t)(dir * NC_ + c) * B_ + b;
    g_dts[base * D_ + d] = dts;
    #pragma unroll
    for (int s = 0; s < S_; s++)
        g_hfin[(base * S_ + s) * D_ + d] = h[s];
}

// Phase B
__global__ void __launch_bounds__(256)
scan_combine(const float* __restrict__ Alogf, const float* __restrict__ Alogb)
{
    const int idx = blockIdx.x * 256 + threadIdx.x;
    const int dir = idx >> 13;
    const int b   = (idx >> 9) & 15;
    const int d   = idx & 511;

    float a[S_], a0; bool structured;
    load_a(dir ? Alogb : Alogf, d, a, a0, structured);

    float h[S_];
    #pragma unroll
    for (int s = 0; s < S_; s++) h[s] = 0.f;

    for (int c = 0; c < NC_; c++) {
        const size_t base = (size_t)(dir * NC_ + c) * B_ + b;
        #pragma unroll
        for (int s = 0; s < S_; s++)
            g_h0[(base * S_ + s) * D_ + d] = h[s];
        const float dts = g_dts[base * D_ + d];
        float P[16];
        calc_P(structured, a0, a, dts, P);
        #pragma unroll
        for (int s = 0; s < S_; s++)
            h[s] = fmaf(P[s], h[s], g_hfin[(base * S_ + s) * D_ + d]);
    }
}

// Phase C
__global__ void __launch_bounds__(128)
scan_final(const float* __restrict__ Alogf, const float* __restrict__ Alogb,
           const float* __restrict__ Dskf,  const float* __restrict__ Dskb)
{
    const int bx  = blockIdx.x;
    const int db  = bx & 3;
    const int c   = bx >> 2;
    const int d   = db * 128 + threadIdx.x;
    const int b   = blockIdx.y;
    const int dir = blockIdx.z;

    float a[S_], a0; bool structured;
    load_a(dir ? Alogb : Alogf, d, a, a0, structured);
    const float Dsk = (dir ? Dskb : Dskf)[d];

    const size_t base = (size_t)(dir * NC_ + c) * B_ + b;
    float h[S_];
    #pragma unroll
    for (int s = 0; s < S_; s++)
        h[s] = g_h0[(base * S_ + s) * D_ + d];

    for (int t = c * CH_; t < c * CH_ + CH_; t++) {
        const int tt = dir ? (T_ - 1 - t) : t;
        const size_t rb = (size_t)b * T_ + tt;
        const float dtv = g_dtcat[rb * 1024 + dir * 512 + d];
        const float u   = g_enc[rb * D_ + d];
        const float du  = dtv * u;

        const float4* v4 = reinterpret_cast<const float4*>(g_xz + rb * 128 + dir * 64 + 32);
        float4 B0 = v4[0], B1 = v4[1], B2 = v4[2], B3 = v4[3];
        float4 C0 = v4[4], C1 = v4[5], C2 = v4[6], C3 = v4[7];
        float bc[16] = {B0.x,B0.y,B0.z,B0.w, B1.x,B1.y,B1.z,B1.w,
                        B2.x,B2.y,B2.z,B2.w, B3.x,B3.y,B3.z,B3.w};
        float cc[16] = {C0.x,C0.y,C0.z,C0.w, C1.x,C1.y,C1.z,C1.w,
                        C2.x,C2.y,C2.z,C2.w, C3.x,C3.y,C3.z,C3.w};

        float P[16];
        calc_P(structured, a0, a, dtv, P);

        float acc0 = 0.f, acc1 = 0.f, acc2 = 0.f, acc3 = 0.f;
        #pragma unroll
        for (int s = 0; s < 16; s += 4) {
            h[s+0] = fmaf(P[s+0], h[s+0], du * bc[s+0]);
            h[s+1] = fmaf(P[s+1], h[s+1], du * bc[s+1]);
            h[s+2] = fmaf(P[s+2], h[s+2], du * bc[s+2]);
            h[s+3] = fmaf(P[s+3], h[s+3], du * bc[s+3]);
            acc0 = fmaf(h[s+0], cc[s+0], acc0);
            acc1 = fmaf(h[s+1], cc[s+1], acc1);
            acc2 = fmaf(h[s+2], cc[s+2], acc2);
            acc3 = fmaf(h[s+3], cc[s+3], acc3);
        }
        float y = (acc0 + acc1) + (acc2 + acc3) + u * Dsk;
        g_ycat[rb * 1024 + dir * 512 + d] = y;

        float ynb = __shfl_xor_sync(0xffffffffu, y, 1);
        if ((threadIdx.x & 1) == 0) {
            size_t o = rb * 512 + ((dir * 512 + d) >> 1);
            bf16_split_pair(y, ynb, g_ycatH[o], g_ycatL[o]);
        }
    }
}

// ---------------------------------------------------------------------------
// LayerNorm over D -> bf16 pair planes
// ---------------------------------------------------------------------------
__global__ void ln_kernel(const float* __restrict__ gamma, const float* __restrict__ beta)
{
    __shared__ float r1[256];
    __shared__ float r2[256];
    __shared__ float mu_s, rs_s;
    const int row = blockIdx.x;
    const int tid = threadIdx.x;
    const float2 vv = reinterpret_cast<const float2*>(g_hbuf + (size_t)row * D_)[tid];
    r1[tid] = vv.x + vv.y;
    r2[tid] = vv.x * vv.x + vv.y * vv.y;
    __syncthreads();
    for (int off = 128; off > 0; off >>= 1) {
        if (tid < off) { r1[tid] += r1[tid + off]; r2[tid] += r2[tid + off]; }
        __syncthreads();
    }
    if (tid == 0) {
        float mu  = r1[0] / (float)D_;
        float var = r2[0] / (float)D_ - mu * mu;
        mu_s = mu;
        rs_s = rsqrtf(var + 1e-5f);
    }
    __syncthreads();
    float mu = mu_s, rs = rs_s;
    float o0 = (vv.x - mu) * rs * gamma[2 * tid]     + beta[2 * tid];
    float o1 = (vv.y - mu) * rs * gamma[2 * tid + 1] + beta[2 * tid + 1];
    size_t o = (size_t)row * 256 + tid;
    bf16_split_pair(o0, o1, g_hnH[o], g_hnL[o]);
}

// ---------------------------------------------------------------------------
// output transpose + de-normalize
// ---------------------------------------------------------------------------
__global__ void out_kernel(float* __restrict__ out)
{
    int idx = blockIdx.x * 256 + threadIdx.x;
    if (idx >= B_ * PRED_ * N_) return;
    int n = idx % N_;
    int p = (idx / N_) % PRED_;
    int b = idx / (N_ * PRED_);
    float v = g_pre[((size_t)b * T_ + n) * PRED_ + p];
    out[idx] = v * g_std[b * N_ + n] + g_mean[b * N_ + n];
}

// ---------------------------------------------------------------------------
// launch
// ---------------------------------------------------------------------------
extern "C" void kernel_launch(void* const* d_in, const int* in_sizes, int n_in,
                              void* d_out, int out_size)
{
    const float* x_enc  = (const float*)d_in[0];
    const float* x_mark = (const float*)d_in[1];
    const float* W_emb  = (const float*)d_in[4];
    const float* b_emb  = (const float*)d_in[5];
    const float* Alogf  = (const float*)d_in[6];
    const float* Wx_f   = (const float*)d_in[7];
    const float* Wdt_f  = (const float*)d_in[8];
    const float* bdt_f  = (const float*)d_in[9];
    const float* Dsk_f  = (const float*)d_in[10];
    const float* Alogb  = (const float*)d_in[11];
    const float* Wx_b   = (const float*)d_in[12];
    const float* Wdt_b  = (const float*)d_in[13];
    const float* bdt_b  = (const float*)d_in[14];
    const float* Dsk_b  = (const float*)d_in[15];
    const float* Wz     = (const float*)d_in[16];
    const float* bz     = (const float*)d_in[17];
    const float* Wo     = (const float*)d_in[18];
    const float* bo     = (const float*)d_in[19];
    const float* lng    = (const float*)d_in[20];
    const float* lnb    = (const float*)d_in[21];
    const float* Wproj  = (const float*)d_in[22];
    const float* bproj  = (const float*)d_in[23];
    float* out = (float*)d_out;

    float *enc, *xz, *dtc, *ycat, *hb, *pre, *bdt;
    uint32_t *tokH,*tokL,*encH,*encL,*xzH,*xzL,*ycatH,*ycatL,*fusH,*fusL,*hnH,*hnL;
    uint32_t *wembH,*wembL,*wxH,*wxL,*wdtH,*wdtL,*wzH,*wzL,*woH,*woL,*wpjH,*wpjL;
    cudaGetSymbolAddress((void**)&enc,   g_enc);
    cudaGetSymbolAddress((void**)&xz,    g_xz);
    cudaGetSymbolAddress((void**)&dtc,   g_dtcat);
    cudaGetSymbolAddress((void**)&ycat,  g_ycat);
    cudaGetSymbolAddress((void**)&hb,    g_hbuf);
    cudaGetSymbolAddress((void**)&pre,   g_pre);
    cudaGetSymbolAddress((void**)&bdt,   g_bdt);
    cudaGetSymbolAddress((void**)&tokH,  g_tokH);  cudaGetSymbolAddress((void**)&tokL,  g_tokL);
    cudaGetSymbolAddress((void**)&encH,  g_encH);  cudaGetSymbolAddress((void**)&encL,  g_encL);
    cudaGetSymbolAddress((void**)&xzH,   g_xzH);   cudaGetSymbolAddress((void**)&xzL,   g_xzL);
    cudaGetSymbolAddress((void**)&ycatH, g_ycatH); cudaGetSymbolAddress((void**)&ycatL, g_ycatL);
    cudaGetSymbolAddress((void**)&fusH,  g_fusH);  cudaGetSymbolAddress((void**)&fusL,  g_fusL);
    cudaGetSymbolAddress((void**)&hnH,   g_hnH);   cudaGetSymbolAddress((void**)&hnL,   g_hnL);
    cudaGetSymbolAddress((void**)&wembH, g_wembH); cudaGetSymbolAddress((void**)&wembL, g_wembL);
    cudaGetSymbolAddress((void**)&wxH,   g_wxH);   cudaGetSymbolAddress((void**)&wxL,   g_wxL);
    cudaGetSymbolAddress((void**)&wdtH,  g_wdtH);  cudaGetSymbolAddress((void**)&wdtL,  g_wdtL);
    cudaGetSymbolAddress((void**)&wzH,   g_wzH);   cudaGetSymbolAddress((void**)&wzL,   g_wzL);
    cudaGetSymbolAddress((void**)&woH,   g_woH);   cudaGetSymbolAddress((void**)&woL,   g_woL);
    cudaGetSymbolAddress((void**)&wpjH,  g_wpjH);  cudaGetSymbolAddress((void**)&wpjL,  g_wpjL);

    cudaFuncSetAttribute(gemm_bf<EPI_NONE>,     cudaFuncAttributeMaxDynamicSharedMemorySize, GEMM_SMEM);
    cudaFuncSetAttribute(gemm_bf<EPI_SOFTPLUS>, cudaFuncAttributeMaxDynamicSharedMemorySize, GEMM_SMEM);
    cudaFuncSetAttribute(gemm_bf<EPI_SIGFUSE>,  cudaFuncAttributeMaxDynamicSharedMemorySize, GEMM_SMEM);
    cudaFuncSetAttribute(gemm_bf<EPI_ADD>,      cudaFuncAttributeMaxDynamicSharedMemorySize, GEMM_SMEM);

    const int gy = (MROWS + 63) / 64;   // 82

    // 0) weight pre-split
    split_weights<<<(I_ALL + 255) / 256, 256>>>(
        W_emb, Wx_f, Wx_b, Wdt_f, Wdt_b, Wz, Wo, Wproj, bdt_f, bdt_b);

    // 1) stats
    stats_kernel<<<dim3(B_, (N_ + 31) / 32), 256>>>(x_enc);

    // 2) tok planes
    build_tok<<<dim3((T_ + 31) / 32, L_ / 32, B_), dim3(32, 8)>>>(x_enc, x_mark);

    // 3) enc = tok @ W_emb + b_emb
    gemm_bf<EPI_NONE><<<dim3(D_ / 128, gy), 256, GEMM_SMEM>>>(
        tokH, tokL, 256, wembH, wembL, 256, enc, D_, encH, encL, 256,
        MROWS, D_, 512, b_emb, nullptr, nullptr, 0);

    // 4) xz = enc @ [Wx_f|Wx_b]
    gemm_bf<EPI_NONE><<<dim3(1, gy), 256, GEMM_SMEM>>>(
        encH, encL, 256, wxH, wxL, 256, xz, 128, xzH, xzL, 64,
        MROWS, 128, 512, nullptr, nullptr, nullptr, 0);

    // 5) dtcat = softplus(xz @ Wdt_blockdiag + bdt)
    gemm_bf<EPI_SOFTPLUS><<<dim3(8, gy), 256, GEMM_SMEM>>>(
        xzH, xzL, 64, wdtH, wdtL, 64, dtc, 1024, nullptr, nullptr, 0,
        MROWS, 1024, 128, bdt, nullptr, nullptr, 0);

    // 6) chunked bidirectional scan
    scan_partial<<<dim3(4 * NC_, B_, 2), 128>>>(Alogf, Alogb);
    scan_combine<<<64, 256>>>(Alogf, Alogb);
    scan_final  <<<dim3(4 * NC_, B_, 2), 128>>>(Alogf, Alogb, Dsk_f, Dsk_b);

    // 7) fused = sigmoid(ycat @ Wz + bz) gate
    gemm_bf<EPI_SIGFUSE><<<dim3(D_ / 128, gy), 256, GEMM_SMEM>>>(
        ycatH, ycatL, 512, wzH, wzL, 512, nullptr, 0, fusH, fusL, 256,
        MROWS, D_, 1024, bz, ycat, ycat + D_, 2 * D_);

    // 8) h = enc + fused @ Wo + bo
    gemm_bf<EPI_ADD><<<dim3(D_ / 128, gy), 256, GEMM_SMEM>>>(
        fusH, fusL, 256, woH, woL, 256, hb, D_, nullptr, nullptr, 0,
        MROWS, D_, 512, bo, enc, nullptr, D_);

    // 9) layernorm -> hn planes
    ln_kernel<<<MROWS, 256>>>(lng, lnb);

    // 10) pre = hn @ W_proj + b_proj
    gemm_bf<EPI_NONE><<<dim3(1, gy), 256, GEMM_SMEM>>>(
        hnH, hnL, 256, wpjH, wpjL, 256, pre, PRED_, nullptr, nullptr, 0,
        MROWS, PRED_, 512, bproj, nullptr, nullptr, 0);

    // 11) output
    out_kernel<<<(B_ * PRED_ * N_ + 255) / 256, 256>>>(out);
}

// round 12
// speedup vs baseline: 1.0001x; 1.0001x over previous
#include <cuda_runtime.h>
#include <cuda_bf16.h>
#include <math.h>
#include <stdint.h>

// ---------------------------------------------------------------------------
// Problem dims
// ---------------------------------------------------------------------------
namespace {
constexpr int B_   = 16;
constexpr int L_   = 512;
constexpr int N_   = 321;
constexpr int MK_  = 4;
constexpr int D_   = 512;
constexpr int S_   = 16;
constexpr int DTR_ = 32;
constexpr int PRED_= 96;
constexpr int T_   = N_ + MK_;        // 325
constexpr int MROWS = B_ * T_;        // 5200
constexpr int NC_  = 13;
constexpr int CH_  = 25;
}

// ---------------------------------------------------------------------------
// fp32 scratch
// ---------------------------------------------------------------------------
__device__ float g_mean[B_ * N_];
__device__ float g_istd[B_ * N_];
__device__ float g_std [B_ * N_];
__device__ float g_enc  [(size_t)MROWS * D_];
__device__ float g_xz   [(size_t)MROWS * 128];
__device__ float g_dtcat[(size_t)MROWS * 1024];
__device__ float g_ycat [(size_t)MROWS * 2 * D_];
__device__ float g_hbuf [(size_t)MROWS * D_];
__device__ float g_pre  [(size_t)MROWS * PRED_];

// bf16 (hi,lo) packed-pair planes: u32 = 2 consecutive-K bf16.
__device__ uint32_t g_tokH [(size_t)MROWS * 256],  g_tokL [(size_t)MROWS * 256];
__device__ uint32_t g_encH [(size_t)MROWS * 256],  g_encL [(size_t)MROWS * 256];
__device__ uint32_t g_xzH  [(size_t)MROWS * 64],   g_xzL  [(size_t)MROWS * 64];
__device__ uint32_t g_ycatH[(size_t)MROWS * 512],  g_ycatL[(size_t)MROWS * 512];
__device__ uint32_t g_fusH [(size_t)MROWS * 256],  g_fusL [(size_t)MROWS * 256];
__device__ uint32_t g_hnH  [(size_t)MROWS * 256],  g_hnL  [(size_t)MROWS * 256];

// weight planes, [N][K/2] u32
__device__ uint32_t g_wembH[512 * 256],  g_wembL[512 * 256];
__device__ uint32_t g_wxH  [128 * 256],  g_wxL  [128 * 256];
__device__ uint32_t g_wdtH [1024 * 64],  g_wdtL [1024 * 64];
__device__ uint32_t g_wzH  [512 * 512],  g_wzL  [512 * 512];
__device__ uint32_t g_woH  [512 * 256],  g_woL  [512 * 256];
__device__ uint32_t g_wpjH [96 * 256],   g_wpjL [96 * 256];
__device__ float    g_bdt  [1024];

// chunked-scan intermediates
__device__ float g_dts [2 * NC_ * B_ * D_];
__device__ float g_hfin[(size_t)2 * NC_ * B_ * S_ * D_];
__device__ float g_h0  [(size_t)2 * NC_ * B_ * S_ * D_];

// ---------------------------------------------------------------------------
// bf16 split helper
// ---------------------------------------------------------------------------
__device__ __forceinline__ void bf16_split_pair(float x0, float x1,
                                                uint32_t& hi, uint32_t& lo)
{
    __nv_bfloat16 h0 = __float2bfloat16(x0);
    __nv_bfloat16 h1 = __float2bfloat16(x1);
    __nv_bfloat16 l0 = __float2bfloat16(x0 - __bfloat162float(h0));
    __nv_bfloat16 l1 = __float2bfloat16(x1 - __bfloat162float(h1));
    __nv_bfloat162 hp, lp;
    hp.x = h0; hp.y = h1;
    lp.x = l0; lp.y = l1;
    hi = *reinterpret_cast<uint32_t*>(&hp);
    lo = *reinterpret_cast<uint32_t*>(&lp);
}

// ---------------------------------------------------------------------------
// 0) weight split
// ---------------------------------------------------------------------------
namespace {
constexpr int I_EMB = 512 * 256;
constexpr int I_WX  = 128 * 256;
constexpr int I_WDT = 1024 * 64;
constexpr int I_WZ  = 512 * 512;
constexpr int I_WO  = 512 * 256;
constexpr int I_WPJ = 96 * 256;
constexpr int I_ALL = I_EMB + I_WX + I_WDT + I_WZ + I_WO + I_WPJ + 1024;
}

__global__ void split_weights(const float* __restrict__ Wemb,
                              const float* __restrict__ Wxf,  const float* __restrict__ Wxb,
                              const float* __restrict__ Wdtf, const float* __restrict__ Wdtb,
                              const float* __restrict__ Wz,   const float* __restrict__ Wo,
                              const float* __restrict__ Wproj,
                              const float* __restrict__ bdtf, const float* __restrict__ bdtb)
{
    int i = blockIdx.x * 256 + threadIdx.x;
    if (i < I_EMB) {
        int n = i >> 8, kp = i & 255;
        bf16_split_pair(Wemb[(2*kp)*512 + n], Wemb[(2*kp+1)*512 + n], g_wembH[i], g_wembL[i]);
        return;
    }
    i -= I_EMB;
    if (i < I_WX) {
        int n = i >> 8, kp = i & 255;
        float v0, v1;
        if (n < 64) { v0 = Wxf[(2*kp)*64 + n];       v1 = Wxf[(2*kp+1)*64 + n]; }
        else        { v0 = Wxb[(2*kp)*64 + n - 64];  v1 = Wxb[(2*kp+1)*64 + n - 64]; }
        bf16_split_pair(v0, v1, g_wxH[i], g_wxL[i]);
        return;
    }
    i -= I_WX;
    if (i < I_WDT) {
        int n = i >> 6, kp = i & 63;
        int k0 = 2 * kp, k1 = k0 + 1;
        float v0 = 0.f, v1 = 0.f;
        if (n < 512) {
            if (k0 < 32) v0 = Wdtf[k0 * 512 + n];
            if (k1 < 32) v1 = Wdtf[k1 * 512 + n];
        } else {
            if (k0 >= 64 && k0 < 96) v0 = Wdtb[(k0 - 64) * 512 + n - 512];
            if (k1 >= 64 && k1 < 96) v1 = Wdtb[(k1 - 64) * 512 + n - 512];
        }
        bf16_split_pair(v0, v1, g_wdtH[i], g_wdtL[i]);
        return;
    }
    i -= I_WDT;
    if (i < I_WZ) {
        int n = i >> 9, kp = i & 511;
        bf16_split_pair(Wz[(2*kp)*512 + n], Wz[(2*kp+1)*512 + n], g_wzH[i], g_wzL[i]);
        return;
    }
    i -= I_WZ;
    if (i < I_WO) {
        int n = i >> 8, kp = i & 255;
        bf16_split_pair(Wo[(2*kp)*512 + n], Wo[(2*kp+1)*512 + n], g_woH[i], g_woL[i]);
        return;
    }
    i -= I_WO;
    if (i < I_WPJ) {
        int n = i >> 8, kp = i & 255;
        bf16_split_pair(Wproj[(2*kp)*PRED_ + n], Wproj[(2*kp+1)*PRED_ + n], g_wpjH[i], g_wpjL[i]);
        return;
    }
    i -= I_WPJ;
    if (i < 1024) g_bdt[i] = (i < 512) ? bdtf[i] : bdtb[i - 512];
}

// ---------------------------------------------------------------------------
// 1) stats
// ---------------------------------------------------------------------------
__global__ void stats_kernel(const float* __restrict__ x)
{
    __shared__ float sh1[8][32];
    __shared__ float sh2[8][32];
    const int b  = blockIdx.x;
    const int tx = threadIdx.x & 31;
    const int lg = threadIdx.x >> 5;
    const int n  = blockIdx.y * 32 + tx;

    float s = 0.f, s2 = 0.f;
    if (n < N_) {
        #pragma unroll 4
        for (int l = lg; l < L_; l += 8) {
            float v = x[((size_t)b * L_ + l) * N_ + n];
            s  += v;
            s2 += v * v;
        }
    }
    sh1[lg][tx] = s;
    sh2[lg][tx] = s2;
    __syncthreads();
    if (lg == 0 && n < N_) {
        float S1 = 0.f, S2 = 0.f;
        #pragma unroll
        for (int r = 0; r < 8; r++) { S1 += sh1[r][tx]; S2 += sh2[r][tx]; }
        float mu  = S1 / (float)L_;
        float var = S2 / (float)L_ - mu * mu;
        float sd  = sqrtf(var + 1e-5f);
        g_mean[b * N_ + n] = mu;
        g_std [b * N_ + n] = sd;
        g_istd[b * N_ + n] = 1.f / sd;
    }
}

// ---------------------------------------------------------------------------
// 2) tok build -> planes
// ---------------------------------------------------------------------------
__global__ void build_tok(const float* __restrict__ xe, const float* __restrict__ xm)
{
    __shared__ float tile[32][33];
    const int b  = blockIdx.z;
    const int tx = threadIdx.x, ty = threadIdx.y;
    const int t0 = blockIdx.x * 32;
    const int l0 = blockIdx.y * 32;
    const int tid = ty * 32 + tx;

    #pragma unroll
    for (int j = 0; j < 4; j++) {
        int l = l0 + ty + 8 * j;
        int t = t0 + tx;
        float v = 0.f;
        if (t < T_) {
            if (t < N_) v = (xe[((size_t)b * L_ + l) * N_ + t] - g_mean[b * N_ + t]) * g_istd[b * N_ + t];
            else        v = xm[((size_t)b * L_ + l) * MK_ + (t - N_)];
        }
        tile[ty + 8 * j][tx] = v;
    }
    __syncthreads();
    #pragma unroll
    for (int it = 0; it < 2; it++) {
        int item = tid + it * 256;
        int tl = item & 31;
        int lp = item >> 5;
        int t  = t0 + tl;
        if (t < T_) {
            size_t o = ((size_t)b * T_ + t) * 256 + (l0 >> 1) + lp;
            bf16_split_pair(tile[2*lp][tl], tile[2*lp+1][tl], g_tokH[o], g_tokL[o]);
        }
    }
}

// ---------------------------------------------------------------------------
// mma / cp.async helpers
// ---------------------------------------------------------------------------
__device__ __forceinline__ void mma_bf16(float* c, const uint32_t* a,
                                         uint32_t b0, uint32_t b1)
{
    asm volatile(
        "mma.sync.aligned.m16n8k16.row.col.f32.bf16.bf16.f32 "
        "{%0,%1,%2,%3},{%4,%5,%6,%7},{%8,%9},{%0,%1,%2,%3};\n"
        : "+f"(c[0]), "+f"(c[1]), "+f"(c[2]), "+f"(c[3])
        : "r"(a[0]), "r"(a[1]), "r"(a[2]), "r"(a[3]), "r"(b0), "r"(b1));
}

__device__ __forceinline__ void cp_async16(void* smem_dst, const void* gsrc, int src_bytes)
{
    uint32_t saddr = (uint32_t)__cvta_generic_to_shared(smem_dst);
    asm volatile("cp.async.cg.shared.global [%0], [%1], 16, %2;\n"
                 :: "r"(saddr), "l"(gsrc), "r"(src_bytes));
}
__device__ __forceinline__ void cp_commit() { asm volatile("cp.async.commit_group;\n"); }
template<int NN>
__device__ __forceinline__ void cp_wait() { asm volatile("cp.async.wait_group %0;\n" :: "n"(NN)); }

// ---------------------------------------------------------------------------
// bf16x3 tensor-core GEMM, term-major MMA issue (dependency distance 8).
// BM=64 BN=128 BK=32, 256 threads (8 warps, 2x4 grid, 32x32 warp tiles).
// 3-stage cp.async pipeline, one sync per k-tile.
// ---------------------------------------------------------------------------
constexpr int EPI_NONE = 0, EPI_SOFTPLUS = 1, EPI_SIGFUSE = 2, EPI_ADD = 3;
constexpr int LDK  = 20;
constexpr int A_PL = 64 * LDK;
constexpr int B_PL = 128 * LDK;
constexpr int STG_U = 2 * A_PL + 2 * B_PL;                    // 7680 u32
constexpr int STAGES = 3;
constexpr int GEMM_SMEM = STAGES * STG_U * (int)sizeof(uint32_t);  // 92160 B

template<int EPI>
__global__ void __launch_bounds__(256, 2)
gemm_bf(const uint32_t* __restrict__ Ahi, const uint32_t* __restrict__ Alo, int ldaU,
        const uint32_t* __restrict__ Bhi, const uint32_t* __restrict__ Blo, int ldbU,
        float* __restrict__ C, int ldc,
        uint32_t* __restrict__ CHi, uint32_t* __restrict__ CLo, int ldcU,
        int M, int Ncols, int K,
        const float* __restrict__ bias,
        const float* __restrict__ e1,
        const float* __restrict__ e2,
        int elds)
{
    constexpr int BM = 64, BN = 128, BK = 32;
    extern __shared__ uint32_t smu[];

    const int tid = threadIdx.x;
    const int w   = tid >> 5, l = tid & 31;
    const int g   = l >> 2, tg = l & 3;
    const int wr  = w >> 2, wc = w & 3;
    const int m0w = wr * 32, n0w = wc * 32;
    const int rowBase = blockIdx.y * BM;
    const int colBase = blockIdx.x * BN;

    float acc[2][4][4];
    #pragma unroll
    for (int mi = 0; mi < 2; mi++)
        #pragma unroll
        for (int ni = 0; ni < 4; ni++)
            #pragma unroll
            for (int q = 0; q < 4; q++) acc[mi][ni][q] = 0.f;

    const int KT = K / BK;

    auto load_tile = [&](int kt, int stage) {
        uint32_t* sA = smu + stage * STG_U;
        uint32_t* sB = sA + 2 * A_PL;
        const int kp0 = kt * (BK / 2);
        #pragma unroll
        for (int j = 0; j < 2; j++) {
            int idx = tid + j * 256;
            int c   = idx & 3;
            int row = (idx >> 2) & 63;
            int pl  = idx >> 8;
            int gr  = rowBase + row;
            int sz  = (gr < M) ? 16 : 0;
            int grc = (gr < M) ? gr : 0;
            const uint32_t* src = (pl ? Alo : Ahi) + (size_t)grc * ldaU + kp0 + c * 4;
            cp_async16(sA + pl * A_PL + row * LDK + c * 4, src, sz);
        }
        #pragma unroll
        for (int j = 0; j < 4; j++) {
            int idx = tid + j * 256;
            int c   = idx & 3;
            int n   = (idx >> 2) & 127;
            int pl  = idx >> 9;
            int gn  = colBase + n;
            int sz  = (gn < Ncols) ? 16 : 0;
            int gnc = (gn < Ncols) ? gn : 0;
            const uint32_t* src = (pl ? Blo : Bhi) + (size_t)gnc * ldbU + kp0 + c * 4;
            cp_async16(sB + pl * B_PL + n * LDK + c * 4, src, sz);
        }
    };

    load_tile(0, 0);
    cp_commit();
    if (KT > 1) load_tile(1, 1);
    cp_commit();

    for (int kt = 0; kt < KT; kt++) {
        cp_wait<STAGES - 2>();
        __syncthreads();

        const int knext = kt + STAGES - 1;
        if (knext < KT) load_tile(knext, knext % STAGES);
        cp_commit();

        const uint32_t* sAh = smu + (kt % STAGES) * STG_U;
        const uint32_t* sAl = sAh + A_PL;
        const uint32_t* sBh = sAh + 2 * A_PL;
        const uint32_t* sBl = sBh + B_PL;

        #pragma unroll
        for (int ks = 0; ks < 2; ks++) {
            const int kb = ks * 8;
            // load ALL fragments first
            uint32_t ah[2][4], al[2][4];
            #pragma unroll
            for (int mi = 0; mi < 2; mi++) {
                const int r0 = m0w + mi * 16 + g;
                ah[mi][0] = sAh[(r0    ) * LDK + kb + tg    ];
                ah[mi][1] = sAh[(r0 + 8) * LDK + kb + tg    ];
                ah[mi][2] = sAh[(r0    ) * LDK + kb + tg + 4];
                ah[mi][3] = sAh[(r0 + 8) * LDK + kb + tg + 4];
                al[mi][0] = sAl[(r0    ) * LDK + kb + tg    ];
                al[mi][1] = sAl[(r0 + 8) * LDK + kb + tg    ];
                al[mi][2] = sAl[(r0    ) * LDK + kb + tg + 4];
                al[mi][3] = sAl[(r0 + 8) * LDK + kb + tg + 4];
            }
            uint32_t bh[4][2], bl[4][2];
            #pragma unroll
            for (int ni = 0; ni < 4; ni++) {
                const int n = n0w + ni * 8 + g;
                bh[ni][0] = sBh[n * LDK + kb + tg    ];
                bh[ni][1] = sBh[n * LDK + kb + tg + 4];
                bl[ni][0] = sBl[n * LDK + kb + tg    ];
                bl[ni][1] = sBl[n * LDK + kb + tg + 4];
            }
            // term-major issue: 8 independent MMAs between same-acc reuse
            #pragma unroll
            for (int ni = 0; ni < 4; ni++)
                #pragma unroll
                for (int mi = 0; mi < 2; mi++)
                    mma_bf16(acc[mi][ni], ah[mi], bl[ni][0], bl[ni][1]);   // Ah*Bl
            #pragma unroll
            for (int ni = 0; ni < 4; ni++)
                #pragma unroll
                for (int mi = 0; mi < 2; mi++)
                    mma_bf16(acc[mi][ni], al[mi], bh[ni][0], bh[ni][1]);   // Al*Bh
            #pragma unroll
            for (int ni = 0; ni < 4; ni++)
                #pragma unroll
                for (int mi = 0; mi < 2; mi++)
                    mma_bf16(acc[mi][ni], ah[mi], bh[ni][0], bh[ni][1]);   // Ah*Bh
        }
    }

    // epilogue
    #pragma unroll
    for (int mi = 0; mi < 2; mi++) {
        #pragma unroll
        for (int half = 0; half < 2; half++) {
            int gr = rowBase + m0w + mi * 16 + g + half * 8;
            if (gr >= M) continue;
            #pragma unroll
            for (int ni = 0; ni < 4; ni++) {
                int gc = colBase + n0w + ni * 8 + 2 * tg;
                if (gc >= Ncols) continue;
                float x0 = acc[mi][ni][half * 2 + 0];
                float x1 = acc[mi][ni][half * 2 + 1];
                if (bias) { x0 += bias[gc]; x1 += bias[gc + 1]; }
                if (EPI == EPI_SOFTPLUS) {
                    x0 = (x0 > 15.f) ? x0 : log1pf(__expf(x0));
                    x1 = (x1 > 15.f) ? x1 : log1pf(__expf(x1));
                } else if (EPI == EPI_SIGFUSE) {
                    size_t ei = (size_t)gr * elds + gc;
                    float z0 = 1.f / (1.f + __expf(-x0));
                    float z1 = 1.f / (1.f + __expf(-x1));
                    x0 = z0 * e1[ei]     + (1.f - z0) * e2[ei];
                    x1 = z1 * e1[ei + 1] + (1.f - z1) * e2[ei + 1];
                } else if (EPI == EPI_ADD) {
                    size_t ei = (size_t)gr * elds + gc;
                    x0 += e1[ei];
                    x1 += e1[ei + 1];
                }
                if (C) {
                    C[(size_t)gr * ldc + gc]     = x0;
                    C[(size_t)gr * ldc + gc + 1] = x1;
                }
                if (CHi) {
                    size_t o = (size_t)gr * ldcU + (gc >> 1);
                    bf16_split_pair(x0, x1, CHi[o], CLo[o]);
                }
            }
        }
    }
}

// ---------------------------------------------------------------------------
// scan helpers
// ---------------------------------------------------------------------------
__device__ __forceinline__ void load_a(const float* __restrict__ AL, int d,
                                       float* a, float& a0, bool& structured)
{
    #pragma unroll
    for (int s = 0; s < S_; s++) a[s] = -expf(AL[d * S_ + s]);
    a0 = a[0];
    structured = true;
    #pragma unroll
    for (int s = 0; s < S_; s++) {
        float ideal = (float)(s + 1) * a0;
        if (fabsf(a[s] - ideal) > 1e-4f * fabsf(a[s])) structured = false;
    }
}

__device__ __forceinline__ void make_powers(float q, float* P)
{
    float q2 = q * q, q4 = q2 * q2, q8 = q4 * q4;
    P[0] = q;        P[1] = q2;       P[2] = q2 * q;    P[3] = q4;
    P[4] = q4 * q;   P[5] = q4 * q2;  P[6] = q4 * P[2]; P[7] = q8;
    P[8] = q8 * q;   P[9] = q8 * q2;  P[10]= q8 * P[2]; P[11]= q8 * q4;
    P[12]= q8 * P[4];P[13]= q8 * P[5];P[14]= q8 * P[6]; P[15]= q8 * q8;
}

__device__ __forceinline__ void calc_P(bool structured, float a0, const float* a,
                                       float x, float* P)
{
    if (structured) {
        make_powers(__expf(a0 * x), P);
    } else {
        #pragma unroll
        for (int s = 0; s < 16; s++) P[s] = __expf(a[s] * x);
    }
}

__global__ void __launch_bounds__(128)
scan_partial(const float* __restrict__ Alogf, const float* __restrict__ Alogb)
{
    const int bx  = blockIdx.x;
    const int db  = bx & 3;
    const int c   = bx >> 2;
    const int d   = db * 128 + threadIdx.x;
    const int b   = blockIdx.y;
    const int dir = blockIdx.z;

    float a[S_], a0; bool structured;
    load_a(dir ? Alogb : Alogf, d, a, a0, structured);

    float h[S_];
    #pragma unroll
    for (int s = 0; s < S_; s++) h[s] = 0.f;
    float dts = 0.f;

    for (int t = c * CH_; t < c * CH_ + CH_; t++) {
        const int tt = dir ? (T_ - 1 - t) : t;
        const size_t rb = (size_t)b * T_ + tt;
        const float dtv = g_dtcat[rb * 1024 + dir * 512 + d];
        const float u   = g_enc[rb * D_ + d];
        const float du  = dtv * u;
        dts += dtv;

        const float4* v4 = reinterpret_cast<const float4*>(g_xz + rb * 128 + dir * 64 + 32);
        float4 B0 = v4[0], B1 = v4[1], B2 = v4[2], B3 = v4[3];
        float bc[16] = {B0.x,B0.y,B0.z,B0.w, B1.x,B1.y,B1.z,B1.w,
                        B2.x,B2.y,B2.z,B2.w, B3.x,B3.y,B3.z,B3.w};

        float P[16];
        calc_P(structured, a0, a, dtv, P);

        #pragma unroll
        for (int s = 0; s < 16; s++) h[s] = fmaf(P[s], h[s], du * bc[s]);
    }

    const size_t base = (size_t)(dir * NC_ + c) * B_ + b;
    g_dts[base * D_ + d] = dts;
    #pragma unroll
    for (int s = 0; s < S_; s++)
        g_hfin[(base * S_ + s) * D_ + d] = h[s];
}

__global__ void __launch_bounds__(256)
scan_combine(const float* __restrict__ Alogf, const float* __restrict__ Alogb)
{
    const int idx = blockIdx.x * 256 + threadIdx.x;
    const int dir = idx >> 13;
    const int b   = (idx >> 9) & 15;
    const int d   = idx & 511;

    float a[S_], a0; bool structured;
    load_a(dir ? Alogb : Alogf, d, a, a0, structured);

    float h[S_];
    #pragma unroll
    for (int s = 0; s < S_; s++) h[s] = 0.f;

    for (int c = 0; c < NC_; c++) {
        const size_t base = (size_t)(dir * NC_ + c) * B_ + b;
        #pragma unroll
        for (int s = 0; s < S_; s++)
            g_h0[(base * S_ + s) * D_ + d] = h[s];
        const float dts = g_dts[base * D_ + d];
        float P[16];
        calc_P(structured, a0, a, dts, P);
        #pragma unroll
        for (int s = 0; s < S_; s++)
            h[s] = fmaf(P[s], h[s], g_hfin[(base * S_ + s) * D_ + d]);
    }
}

__global__ void __launch_bounds__(128)
scan_final(const float* __restrict__ Alogf, const float* __restrict__ Alogb,
           const float* __restrict__ Dskf,  const float* __restrict__ Dskb)
{
    const int bx  = blockIdx.x;
    const int db  = bx & 3;
    const int c   = bx >> 2;
    const int d   = db * 128 + threadIdx.x;
    const int b   = blockIdx.y;
    const int dir = blockIdx.z;

    float a[S_], a0; bool structured;
    load_a(dir ? Alogb : Alogf, d, a, a0, structured);
    const float Dsk = (dir ? Dskb : Dskf)[d];

    const size_t base = (size_t)(dir * NC_ + c) * B_ + b;
    float h[S_];
    #pragma unroll
    for (int s = 0; s < S_; s++)
        h[s] = g_h0[(base * S_ + s) * D_ + d];

    for (int t = c * CH_; t < c * CH_ + CH_; t++) {
        const int tt = dir ? (T_ - 1 - t) : t;
        const size_t rb = (size_t)b * T_ + tt;
        const float dtv = g_dtcat[rb * 1024 + dir * 512 + d];
        const float u   = g_enc[rb * D_ + d];
        const float du  = dtv * u;

        const float4* v4 = reinterpret_cast<const float4*>(g_xz + rb * 128 + dir * 64 + 32);
        float4 B0 = v4[0], B1 = v4[1], B2 = v4[2], B3 = v4[3];
        float4 C0 = v4[4], C1 = v4[5], C2 = v4[6], C3 = v4[7];
        float bc[16] = {B0.x,B0.y,B0.z,B0.w, B1.x,B1.y,B1.z,B1.w,
                        B2.x,B2.y,B2.z,B2.w, B3.x,B3.y,B3.z,B3.w};
        float cc[16] = {C0.x,C0.y,C0.z,C0.w, C1.x,C1.y,C1.z,C1.w,
                        C2.x,C2.y,C2.z,C2.w, C3.x,C3.y,C3.z,C3.w};

        float P[16];
        calc_P(structured, a0, a, dtv, P);

        float acc0 = 0.f, acc1 = 0.f, acc2 = 0.f, acc3 = 0.f;
        #pragma unroll
        for (int s = 0; s < 16; s += 4) {
            h[s+0] = fmaf(P[s+0], h[s+0], du * bc[s+0]);
            h[s+1] = fmaf(P[s+1], h[s+1], du * bc[s+1]);
            h[s+2] = fmaf(P[s+2], h[s+2], du * bc[s+2]);
            h[s+3] = fmaf(P[s+3], h[s+3], du * bc[s+3]);
            acc0 = fmaf(h[s+0], cc[s+0], acc0);
            acc1 = fmaf(h[s+1], cc[s+1], acc1);
            acc2 = fmaf(h[s+2], cc[s+2], acc2);
            acc3 = fmaf(h[s+3], cc[s+3], acc3);
        }
        float y = (acc0 + acc1) + (acc2 + acc3) + u * Dsk;
        g_ycat[rb * 1024 + dir * 512 + d] = y;

        float ynb = __shfl_xor_sync(0xffffffffu, y, 1);
        if ((threadIdx.x & 1) == 0) {
            size_t o = rb * 512 + ((dir * 512 + d) >> 1);
            bf16_split_pair(y, ynb, g_ycatH[o], g_ycatL[o]);
        }
    }
}

// ---------------------------------------------------------------------------
// LayerNorm -> hn planes
// ---------------------------------------------------------------------------
__global__ void ln_kernel(const float* __restrict__ gamma, const float* __restrict__ beta)
{
    __shared__ float r1[256];
    __shared__ float r2[256];
    __shared__ float mu_s, rs_s;
    const int row = blockIdx.x;
    const int tid = threadIdx.x;
    const float2 vv = reinterpret_cast<const float2*>(g_hbuf + (size_t)row * D_)[tid];
    r1[tid] = vv.x + vv.y;
    r2[tid] = vv.x * vv.x + vv.y * vv.y;
    __syncthreads();
    for (int off = 128; off > 0; off >>= 1) {
        if (tid < off) { r1[tid] += r1[tid + off]; r2[tid] += r2[tid + off]; }
        __syncthreads();
    }
    if (tid == 0) {
        float mu  = r1[0] / (float)D_;
        float var = r2[0] / (float)D_ - mu * mu;
        mu_s = mu;
        rs_s = rsqrtf(var + 1e-5f);
    }
    __syncthreads();
    float mu = mu_s, rs = rs_s;
    float o0 = (vv.x - mu) * rs * gamma[2 * tid]     + beta[2 * tid];
    float o1 = (vv.y - mu) * rs * gamma[2 * tid + 1] + beta[2 * tid + 1];
    size_t o = (size_t)row * 256 + tid;
    bf16_split_pair(o0, o1, g_hnH[o], g_hnL[o]);
}

// ---------------------------------------------------------------------------
// output
// ---------------------------------------------------------------------------
__global__ void out_kernel(float* __restrict__ out)
{
    int idx = blockIdx.x * 256 + threadIdx.x;
    if (idx >= B_ * PRED_ * N_) return;
    int n = idx % N_;
    int p = (idx / N_) % PRED_;
    int b = idx / (N_ * PRED_);
    float v = g_pre[((size_t)b * T_ + n) * PRED_ + p];
    out[idx] = v * g_std[b * N_ + n] + g_mean[b * N_ + n];
}

// ---------------------------------------------------------------------------
// launch
// ---------------------------------------------------------------------------
extern "C" void kernel_launch(void* const* d_in, const int* in_sizes, int n_in,
                              void* d_out, int out_size)
{
    const float* x_enc  = (const float*)d_in[0];
    const float* x_mark = (const float*)d_in[1];
    const float* W_emb  = (const float*)d_in[4];
    const float* b_emb  = (const float*)d_in[5];
    const float* Alogf  = (const float*)d_in[6];
    const float* Wx_f   = (const float*)d_in[7];
    const float* Wdt_f  = (const float*)d_in[8];
    const float* bdt_f  = (const float*)d_in[9];
    const float* Dsk_f  = (const float*)d_in[10];
    const float* Alogb  = (const float*)d_in[11];
    const float* Wx_b   = (const float*)d_in[12];
    const float* Wdt_b  = (const float*)d_in[13];
    const float* bdt_b  = (const float*)d_in[14];
    const float* Dsk_b  = (const float*)d_in[15];
    const float* Wz     = (const float*)d_in[16];
    const float* bz     = (const float*)d_in[17];
    const float* Wo     = (const float*)d_in[18];
    const float* bo     = (const float*)d_in[19];
    const float* lng    = (const float*)d_in[20];
    const float* lnb    = (const float*)d_in[21];
    const float* Wproj  = (const float*)d_in[22];
    const float* bproj  = (const float*)d_in[23];
    float* out = (float*)d_out;

    float *enc, *xz, *dtc, *ycat, *hb, *pre, *bdt;
    uint32_t *tokH,*tokL,*encH,*encL,*xzH,*xzL,*ycatH,*ycatL,*fusH,*fusL,*hnH,*hnL;
    uint32_t *wembH,*wembL,*wxH,*wxL,*wdtH,*wdtL,*wzH,*wzL,*woH,*woL,*wpjH,*wpjL;
    cudaGetSymbolAddress((void**)&enc,   g_enc);
    cudaGetSymbolAddress((void**)&xz,    g_xz);
    cudaGetSymbolAddress((void**)&dtc,   g_dtcat);
    cudaGetSymbolAddress((void**)&ycat,  g_ycat);
    cudaGetSymbolAddress((void**)&hb,    g_hbuf);
    cudaGetSymbolAddress((void**)&pre,   g_pre);
    cudaGetSymbolAddress((void**)&bdt,   g_bdt);
    cudaGetSymbolAddress((void**)&tokH,  g_tokH);  cudaGetSymbolAddress((void**)&tokL,  g_tokL);
    cudaGetSymbolAddress((void**)&encH,  g_encH);  cudaGetSymbolAddress((void**)&encL,  g_encL);
    cudaGetSymbolAddress((void**)&xzH,   g_xzH);   cudaGetSymbolAddress((void**)&xzL,   g_xzL);
    cudaGetSymbolAddress((void**)&ycatH, g_ycatH); cudaGetSymbolAddress((void**)&ycatL, g_ycatL);
    cudaGetSymbolAddress((void**)&fusH,  g_fusH);  cudaGetSymbolAddress((void**)&fusL,  g_fusL);
    cudaGetSymbolAddress((void**)&hnH,   g_hnH);   cudaGetSymbolAddress((void**)&hnL,   g_hnL);
    cudaGetSymbolAddress((void**)&wembH, g_wembH); cudaGetSymbolAddress((void**)&wembL, g_wembL);
    cudaGetSymbolAddress((void**)&wxH,   g_wxH);   cudaGetSymbolAddress((void**)&wxL,   g_wxL);
    cudaGetSymbolAddress((void**)&wdtH,  g_wdtH);  cudaGetSymbolAddress((void**)&wdtL,  g_wdtL);
    cudaGetSymbolAddress((void**)&wzH,   g_wzH);   cudaGetSymbolAddress((void**)&wzL,   g_wzL);
    cudaGetSymbolAddress((void**)&woH,   g_woH);   cudaGetSymbolAddress((void**)&woL,   g_woL);
    cudaGetSymbolAddress((void**)&wpjH,  g_wpjH);  cudaGetSymbolAddress((void**)&wpjL,  g_wpjL);

    cudaFuncSetAttribute(gemm_bf<EPI_NONE>,     cudaFuncAttributeMaxDynamicSharedMemorySize, GEMM_SMEM);
    cudaFuncSetAttribute(gemm_bf<EPI_SOFTPLUS>, cudaFuncAttributeMaxDynamicSharedMemorySize, GEMM_SMEM);
    cudaFuncSetAttribute(gemm_bf<EPI_SIGFUSE>,  cudaFuncAttributeMaxDynamicSharedMemorySize, GEMM_SMEM);
    cudaFuncSetAttribute(gemm_bf<EPI_ADD>,      cudaFuncAttributeMaxDynamicSharedMemorySize, GEMM_SMEM);

    const int gy = (MROWS + 63) / 64;   // 82

    // 0) weight pre-split
    split_weights<<<(I_ALL + 255) / 256, 256>>>(
        W_emb, Wx_f, Wx_b, Wdt_f, Wdt_b, Wz, Wo, Wproj, bdt_f, bdt_b);

    // 1) stats
    stats_kernel<<<dim3(B_, (N_ + 31) / 32), 256>>>(x_enc);

    // 2) tok planes
    build_tok<<<dim3((T_ + 31) / 32, L_ / 32, B_), dim3(32, 8)>>>(x_enc, x_mark);

    // 3) enc = tok @ W_emb + b_emb
    gemm_bf<EPI_NONE><<<dim3(D_ / 128, gy), 256, GEMM_SMEM>>>(
        tokH, tokL, 256, wembH, wembL, 256, enc, D_, encH, encL, 256,
        MROWS, D_, 512, b_emb, nullptr, nullptr, 0);

    // 4) xz = enc @ [Wx_f|Wx_b]
    gemm_bf<EPI_NONE><<<dim3(1, gy), 256, GEMM_SMEM>>>(
        encH, encL, 256, wxH, wxL, 256, xz, 128, xzH, xzL, 64,
        MROWS, 128, 512, nullptr, nullptr, nullptr, 0);

    // 5) dtcat = softplus(xz @ Wdt_blockdiag + bdt)
    gemm_bf<EPI_SOFTPLUS><<<dim3(8, gy), 256, GEMM_SMEM>>>(
        xzH, xzL, 64, wdtH, wdtL, 64, dtc, 1024, nullptr, nullptr, 0,
        MROWS, 1024, 128, bdt, nullptr, nullptr, 0);

    // 6) chunked bidirectional scan
    scan_partial<<<dim3(4 * NC_, B_, 2), 128>>>(Alogf, Alogb);
    scan_combine<<<64, 256>>>(Alogf, Alogb);
    scan_final  <<<dim3(4 * NC_, B_, 2), 128>>>(Alogf, Alogb, Dsk_f, Dsk_b);

    // 7) fused = sigmoid(ycat @ Wz + bz) gate
    gemm_bf<EPI_SIGFUSE><<<dim3(D_ / 128, gy), 256, GEMM_SMEM>>>(
        ycatH, ycatL, 512, wzH, wzL, 512, nullptr, 0, fusH, fusL, 256,
        MROWS, D_, 1024, bz, ycat, ycat + D_, 2 * D_);

    // 8) h = enc + fused @ Wo + bo
    gemm_bf<EPI_ADD><<<dim3(D_ / 128, gy), 256, GEMM_SMEM>>>(
        fusH, fusL, 256, woH, woL, 256, hb, D_, nullptr, nullptr, 0,
        MROWS, D_, 512, bo, enc, nullptr, D_);

    // 9) layernorm -> hn planes
    ln_kernel<<<MROWS, 256>>>(lng, lnb);

    // 10) pre = hn @ W_proj + b_proj
    gemm_bf<EPI_NONE><<<dim3(1, gy), 256, GEMM_SMEM>>>(
        hnH, hnL, 256, wpjH, wpjL, 256, pre, PRED_, nullptr, nullptr, 0,
        MROWS, PRED_, 512, bproj, nullptr, nullptr, 0);

    // 11) output
    out_kernel<<<(B_ * PRED_ * N_ + 255) / 256, 256>>>(out);
}

// round 13
// speedup vs baseline: 1.1754x; 1.1753x over previous
#include <cuda_runtime.h>
#include <cuda.h>
#include <cuda_bf16.h>
#include <math.h>
#include <stdint.h>

// ---------------------------------------------------------------------------
// Problem dims
// ---------------------------------------------------------------------------
namespace {
constexpr int B_   = 16;
constexpr int L_   = 512;
constexpr int N_   = 321;
constexpr int MK_  = 4;
constexpr int D_   = 512;
constexpr int S_   = 16;
constexpr int DTR_ = 32;
constexpr int PRED_= 96;
constexpr int T_   = N_ + MK_;        // 325
constexpr int MROWS = B_ * T_;        // 5200
constexpr int NC_  = 13;
constexpr int CH_  = 25;
}

// ---------------------------------------------------------------------------
// fp32 scratch
// ---------------------------------------------------------------------------
__device__ float g_mean[B_ * N_];
__device__ float g_istd[B_ * N_];
__device__ float g_std [B_ * N_];
__device__ float g_enc  [(size_t)MROWS * D_];
__device__ float g_xz   [(size_t)MROWS * 128];
__device__ float g_dtcat[(size_t)MROWS * 1024];
__device__ float g_ycat [(size_t)MROWS * 2 * D_];
__device__ float g_hbuf [(size_t)MROWS * D_];
__device__ float g_pre  [(size_t)MROWS * PRED_];

// bf16 (hi,lo) packed-pair planes: u32 = 2 consecutive-K bf16.
__device__ uint32_t g_tokH [(size_t)MROWS * 256],  g_tokL [(size_t)MROWS * 256];
__device__ uint32_t g_encH [(size_t)MROWS * 256],  g_encL [(size_t)MROWS * 256];
__device__ uint32_t g_xzH  [(size_t)MROWS * 64],   g_xzL  [(size_t)MROWS * 64];
__device__ uint32_t g_ycatH[(size_t)MROWS * 512],  g_ycatL[(size_t)MROWS * 512];
__device__ uint32_t g_fusH [(size_t)MROWS * 256],  g_fusL [(size_t)MROWS * 256];
__device__ uint32_t g_hnH  [(size_t)MROWS * 256],  g_hnL  [(size_t)MROWS * 256];

// weight planes, [N][K/2] u32
__device__ uint32_t g_wembH[512 * 256],  g_wembL[512 * 256];
__device__ uint32_t g_wxH  [128 * 256],  g_wxL  [128 * 256];
__device__ uint32_t g_wdtH [1024 * 64],  g_wdtL [1024 * 64];
__device__ uint32_t g_wzH  [512 * 512],  g_wzL  [512 * 512];
__device__ uint32_t g_woH  [512 * 256],  g_woL  [512 * 256];
__device__ uint32_t g_wpjH [96 * 256],   g_wpjL [96 * 256];
__device__ float    g_bdt  [1024];

// chunked-scan intermediates
__device__ float g_dts [2 * NC_ * B_ * D_];
__device__ float g_hfin[(size_t)2 * NC_ * B_ * S_ * D_];
__device__ float g_h0  [(size_t)2 * NC_ * B_ * S_ * D_];

// ---------------------------------------------------------------------------
// bf16 split helper
// ---------------------------------------------------------------------------
__device__ __forceinline__ void bf16_split_pair(float x0, float x1,
                                                uint32_t& hi, uint32_t& lo)
{
    __nv_bfloat16 h0 = __float2bfloat16(x0);
    __nv_bfloat16 h1 = __float2bfloat16(x1);
    __nv_bfloat16 l0 = __float2bfloat16(x0 - __bfloat162float(h0));
    __nv_bfloat16 l1 = __float2bfloat16(x1 - __bfloat162float(h1));
    __nv_bfloat162 hp, lp;
    hp.x = h0; hp.y = h1;
    lp.x = l0; lp.y = l1;
    hi = *reinterpret_cast<uint32_t*>(&hp);
    lo = *reinterpret_cast<uint32_t*>(&lp);
}

// ---------------------------------------------------------------------------
// 0) weight split
// ---------------------------------------------------------------------------
namespace {
constexpr int I_EMB = 512 * 256;
constexpr int I_WX  = 128 * 256;
constexpr int I_WDT = 1024 * 64;
constexpr int I_WZ  = 512 * 512;
constexpr int I_WO  = 512 * 256;
constexpr int I_WPJ = 96 * 256;
constexpr int I_ALL = I_EMB + I_WX + I_WDT + I_WZ + I_WO + I_WPJ + 1024;
}

__global__ void split_weights(const float* __restrict__ Wemb,
                              const float* __restrict__ Wxf,  const float* __restrict__ Wxb,
                              const float* __restrict__ Wdtf, const float* __restrict__ Wdtb,
                              const float* __restrict__ Wz,   const float* __restrict__ Wo,
                              const float* __restrict__ Wproj,
                              const float* __restrict__ bdtf, const float* __restrict__ bdtb)
{
    int i = blockIdx.x * 256 + threadIdx.x;
    if (i < I_EMB) {
        int n = i >> 8, kp = i & 255;
        bf16_split_pair(Wemb[(2*kp)*512 + n], Wemb[(2*kp+1)*512 + n], g_wembH[i], g_wembL[i]);
        return;
    }
    i -= I_EMB;
    if (i < I_WX) {
        int n = i >> 8, kp = i & 255;
        float v0, v1;
        if (n < 64) { v0 = Wxf[(2*kp)*64 + n];       v1 = Wxf[(2*kp+1)*64 + n]; }
        else        { v0 = Wxb[(2*kp)*64 + n - 64];  v1 = Wxb[(2*kp+1)*64 + n - 64]; }
        bf16_split_pair(v0, v1, g_wxH[i], g_wxL[i]);
        return;
    }
    i -= I_WX;
    if (i < I_WDT) {
        int n = i >> 6, kp = i & 63;
        int k0 = 2 * kp, k1 = k0 + 1;
        float v0 = 0.f, v1 = 0.f;
        if (n < 512) {
            if (k0 < 32) v0 = Wdtf[k0 * 512 + n];
            if (k1 < 32) v1 = Wdtf[k1 * 512 + n];
        } else {
            if (k0 >= 64 && k0 < 96) v0 = Wdtb[(k0 - 64) * 512 + n - 512];
            if (k1 >= 64 && k1 < 96) v1 = Wdtb[(k1 - 64) * 512 + n - 512];
        }
        bf16_split_pair(v0, v1, g_wdtH[i], g_wdtL[i]);
        return;
    }
    i -= I_WDT;
    if (i < I_WZ) {
        int n = i >> 9, kp = i & 511;
        bf16_split_pair(Wz[(2*kp)*512 + n], Wz[(2*kp+1)*512 + n], g_wzH[i], g_wzL[i]);
        return;
    }
    i -= I_WZ;
    if (i < I_WO) {
        int n = i >> 8, kp = i & 255;
        bf16_split_pair(Wo[(2*kp)*512 + n], Wo[(2*kp+1)*512 + n], g_woH[i], g_woL[i]);
        return;
    }
    i -= I_WO;
    if (i < I_WPJ) {
        int n = i >> 8, kp = i & 255;
        bf16_split_pair(Wproj[(2*kp)*PRED_ + n], Wproj[(2*kp+1)*PRED_ + n], g_wpjH[i], g_wpjL[i]);
        return;
    }
    i -= I_WPJ;
    if (i < 1024) g_bdt[i] = (i < 512) ? bdtf[i] : bdtb[i - 512];
}

// ---------------------------------------------------------------------------
// 1) stats
// ---------------------------------------------------------------------------
__global__ void stats_kernel(const float* __restrict__ x)
{
    __shared__ float sh1[8][32];
    __shared__ float sh2[8][32];
    const int b  = blockIdx.x;
    const int tx = threadIdx.x & 31;
    const int lg = threadIdx.x >> 5;
    const int n  = blockIdx.y * 32 + tx;

    float s = 0.f, s2 = 0.f;
    if (n < N_) {
        #pragma unroll 4
        for (int l = lg; l < L_; l += 8) {
            float v = x[((size_t)b * L_ + l) * N_ + n];
            s  += v;
            s2 += v * v;
        }
    }
    sh1[lg][tx] = s;
    sh2[lg][tx] = s2;
    __syncthreads();
    if (lg == 0 && n < N_) {
        float S1 = 0.f, S2 = 0.f;
        #pragma unroll
        for (int r = 0; r < 8; r++) { S1 += sh1[r][tx]; S2 += sh2[r][tx]; }
        float mu  = S1 / (float)L_;
        float var = S2 / (float)L_ - mu * mu;
        float sd  = sqrtf(var + 1e-5f);
        g_mean[b * N_ + n] = mu;
        g_std [b * N_ + n] = sd;
        g_istd[b * N_ + n] = 1.f / sd;
    }
}

// ---------------------------------------------------------------------------
// 2) tok build -> planes
// ---------------------------------------------------------------------------
__global__ void build_tok(const float* __restrict__ xe, const float* __restrict__ xm)
{
    __shared__ float tile[32][33];
    const int b  = blockIdx.z;
    const int tx = threadIdx.x, ty = threadIdx.y;
    const int t0 = blockIdx.x * 32;
    const int l0 = blockIdx.y * 32;
    const int tid = ty * 32 + tx;

    #pragma unroll
    for (int j = 0; j < 4; j++) {
        int l = l0 + ty + 8 * j;
        int t = t0 + tx;
        float v = 0.f;
        if (t < T_) {
            if (t < N_) v = (xe[((size_t)b * L_ + l) * N_ + t] - g_mean[b * N_ + t]) * g_istd[b * N_ + t];
            else        v = xm[((size_t)b * L_ + l) * MK_ + (t - N_)];
        }
        tile[ty + 8 * j][tx] = v;
    }
    __syncthreads();
    #pragma unroll
    for (int it = 0; it < 2; it++) {
        int item = tid + it * 256;
        int tl = item & 31;
        int lp = item >> 5;
        int t  = t0 + tl;
        if (t < T_) {
            size_t o = ((size_t)b * T_ + t) * 256 + (l0 >> 1) + lp;
            bf16_split_pair(tile[2*lp][tl], tile[2*lp+1][tl], g_tokH[o], g_tokL[o]);
        }
    }
}

// ---------------------------------------------------------------------------
// mma / TMA / mbarrier helpers
// ---------------------------------------------------------------------------
__device__ __forceinline__ void mma_bf16(float* c, const uint32_t* a,
                                         uint32_t b0, uint32_t b1)
{
    asm volatile(
        "mma.sync.aligned.m16n8k16.row.col.f32.bf16.bf16.f32 "
        "{%0,%1,%2,%3},{%4,%5,%6,%7},{%8,%9},{%0,%1,%2,%3};\n"
        : "+f"(c[0]), "+f"(c[1]), "+f"(c[2]), "+f"(c[3])
        : "r"(a[0]), "r"(a[1]), "r"(a[2]), "r"(a[3]), "r"(b0), "r"(b1));
}

__device__ __forceinline__ void tma2d(uint32_t dst, const CUtensorMap* m,
                                      int x, int y, uint32_t bar)
{
    asm volatile(
        "cp.async.bulk.tensor.2d.shared::cta.global.tile.mbarrier::complete_tx::bytes "
        "[%0], [%1, {%2, %3}], [%4];"
        :: "r"(dst), "l"(m), "r"(x), "r"(y), "r"(bar) : "memory");
}

__device__ __forceinline__ void mbar_init(uint32_t bar, uint32_t cnt)
{
    asm volatile("mbarrier.init.shared.b64 [%0], %1;" :: "r"(bar), "r"(cnt) : "memory");
}
__device__ __forceinline__ void mbar_expect_tx(uint32_t bar, uint32_t tx)
{
    asm volatile("mbarrier.arrive.expect_tx.shared.b64 _, [%0], %1;"
                 :: "r"(bar), "r"(tx) : "memory");
}
__device__ __forceinline__ void mbar_wait(uint32_t addr, uint32_t parity)
{
    uint32_t done;
    asm volatile(
        "{\n\t.reg .pred p;\n\t"
        "mbarrier.try_wait.parity.acquire.cta.shared::cta.b64 p, [%1], %2;\n\t"
        "selp.b32 %0, 1, 0, p;\n\t}"
        : "=r"(done) : "r"(addr), "r"(parity) : "memory");
    if (!done) {
        asm volatile(
            "{\n\t.reg .pred P1;\n\t"
            "WAIT_LOOP_%=:\n\t"
            "mbarrier.try_wait.parity.acquire.cta.shared::cta.b64 P1, [%0], %1, 0x989680;\n\t"
            "@P1 bra.uni WAIT_DONE_%=;\n\t"
            "bra.uni WAIT_LOOP_%=;\n\t"
            "WAIT_DONE_%=:\n\t}"
            :: "r"(addr), "r"(parity) : "memory");
    }
}

// ---------------------------------------------------------------------------
// bf16x3 tensor-core GEMM with TMA-loaded SW128-swizzled tiles.
// BM=64 BN=128 BK=64, 256 threads (8 warps, 2x4 grid, 32x32 warp tiles).
// Stage: Ah(8KB) Al(8KB) Bh(16KB) Bl(16KB) = 48KB; 2 stages (96KB dyn smem).
// ---------------------------------------------------------------------------
constexpr int EPI_NONE = 0, EPI_SOFTPLUS = 1, EPI_SIGFUSE = 2, EPI_ADD = 3;
constexpr int STG_U32 = 12288;                 // u32 per stage
constexpr int TX_BYTES = 49152;                // bytes per stage (4 planes)
constexpr int GEMM_SMEM = 2 * STG_U32 * 4;     // 98304

// swizzled smem fragment fetch: plane base (u32*), row, kp (u32 col 0..31)
__device__ __forceinline__ uint32_t frag_at(const uint32_t* p, int r, int kp)
{
    return p[r * 32 + ((((kp >> 2) ^ (r & 7)) << 2) | (kp & 3))];
}

template<int EPI>
__global__ void __launch_bounds__(256, 2)
gemm_tma(const __grid_constant__ CUtensorMap mapAh,
         const __grid_constant__ CUtensorMap mapAl,
         const __grid_constant__ CUtensorMap mapBh,
         const __grid_constant__ CUtensorMap mapBl,
         float* __restrict__ C, int ldc,
         uint32_t* __restrict__ CHi, uint32_t* __restrict__ CLo, int ldcU,
         int M, int Ncols, int K,
         const float* __restrict__ bias,
         const float* __restrict__ e1,
         const float* __restrict__ e2,
         int elds)
{
    extern __shared__ __align__(1024) uint32_t smu[];
    __shared__ __align__(8) uint64_t barArr[2];

    const int tid = threadIdx.x;
    const int w   = tid >> 5, l = tid & 31;
    const int g   = l >> 2, tg = l & 3;
    const int wr  = w >> 2, wc = w & 3;
    const int m0w = wr * 32, n0w = wc * 32;
    const int rowBase = blockIdx.y * 64;
    const int colBase = blockIdx.x * 128;

    const uint32_t smemBase = (uint32_t)__cvta_generic_to_shared(smu);
    const uint32_t barBase  = (uint32_t)__cvta_generic_to_shared(&barArr[0]);

    if (tid == 0) {
        mbar_init(barBase,     1);
        mbar_init(barBase + 8, 1);
    }
    __syncthreads();

    float acc[2][4][4];
    #pragma unroll
    for (int mi = 0; mi < 2; mi++)
        #pragma unroll
        for (int ni = 0; ni < 4; ni++)
            #pragma unroll
            for (int q = 0; q < 4; q++) acc[mi][ni][q] = 0.f;

    const int KT = K / 64;

    auto issue = [&](int kt, int s) {
        const uint32_t st  = smemBase + (uint32_t)(s * STG_U32 * 4);
        const uint32_t bar = barBase + 8 * s;
        mbar_expect_tx(bar, TX_BYTES);
        const int kx = kt * 32;
        tma2d(st,          &mapAh, kx, rowBase, bar);
        tma2d(st + 8192,   &mapAl, kx, rowBase, bar);
        tma2d(st + 16384,  &mapBh, kx, colBase, bar);
        tma2d(st + 32768,  &mapBl, kx, colBase, bar);
    };

    if (tid == 0) {
        issue(0, 0);
        if (KT > 1) issue(1, 1);
    }

    int ph0 = 0, ph1 = 0;

    for (int kt = 0; kt < KT; kt++) {
        const int s = kt & 1;
        if (s == 0) { mbar_wait(barBase,     (uint32_t)ph0); ph0 ^= 1; }
        else        { mbar_wait(barBase + 8, (uint32_t)ph1); ph1 ^= 1; }

        const uint32_t* sAh = smu + s * STG_U32;
        const uint32_t* sAl = sAh + 2048;
        const uint32_t* sBh = sAh + 4096;
        const uint32_t* sBl = sAh + 8192;

        #pragma unroll
        for (int ks = 0; ks < 4; ks++) {
            const int kb = ks * 8;
            const int kp0 = kb + tg, kp1 = kb + tg + 4;
            uint32_t ah[2][4], al[2][4];
            #pragma unroll
            for (int mi = 0; mi < 2; mi++) {
                const int r0 = m0w + mi * 16 + g;
                ah[mi][0] = frag_at(sAh, r0,     kp0);
                ah[mi][1] = frag_at(sAh, r0 + 8, kp0);
                ah[mi][2] = frag_at(sAh, r0,     kp1);
                ah[mi][3] = frag_at(sAh, r0 + 8, kp1);
                al[mi][0] = frag_at(sAl, r0,     kp0);
                al[mi][1] = frag_at(sAl, r0 + 8, kp0);
                al[mi][2] = frag_at(sAl, r0,     kp1);
                al[mi][3] = frag_at(sAl, r0 + 8, kp1);
            }
            uint32_t bh[4][2], bl[4][2];
            #pragma unroll
            for (int ni = 0; ni < 4; ni++) {
                const int n = n0w + ni * 8 + g;
                bh[ni][0] = frag_at(sBh, n, kp0);
                bh[ni][1] = frag_at(sBh, n, kp1);
                bl[ni][0] = frag_at(sBl, n, kp0);
                bl[ni][1] = frag_at(sBl, n, kp1);
            }
            #pragma unroll
            for (int ni = 0; ni < 4; ni++)
                #pragma unroll
                for (int mi = 0; mi < 2; mi++)
                    mma_bf16(acc[mi][ni], ah[mi], bl[ni][0], bl[ni][1]);
            #pragma unroll
            for (int ni = 0; ni < 4; ni++)
                #pragma unroll
                for (int mi = 0; mi < 2; mi++)
                    mma_bf16(acc[mi][ni], al[mi], bh[ni][0], bh[ni][1]);
            #pragma unroll
            for (int ni = 0; ni < 4; ni++)
                #pragma unroll
                for (int mi = 0; mi < 2; mi++)
                    mma_bf16(acc[mi][ni], ah[mi], bh[ni][0], bh[ni][1]);
        }
        __syncthreads();
        if (tid == 0 && kt + 2 < KT) issue(kt + 2, s);
    }

    // epilogue
    #pragma unroll
    for (int mi = 0; mi < 2; mi++) {
        #pragma unroll
        for (int half = 0; half < 2; half++) {
            int gr = rowBase + m0w + mi * 16 + g + half * 8;
            if (gr >= M) continue;
            #pragma unroll
            for (int ni = 0; ni < 4; ni++) {
                int gc = colBase + n0w + ni * 8 + 2 * tg;
                if (gc >= Ncols) continue;
                float x0 = acc[mi][ni][half * 2 + 0];
                float x1 = acc[mi][ni][half * 2 + 1];
                if (bias) { x0 += bias[gc]; x1 += bias[gc + 1]; }
                if (EPI == EPI_SOFTPLUS) {
                    x0 = (x0 > 15.f) ? x0 : log1pf(__expf(x0));
                    x1 = (x1 > 15.f) ? x1 : log1pf(__expf(x1));
                } else if (EPI == EPI_SIGFUSE) {
                    size_t ei = (size_t)gr * elds + gc;
                    float z0 = 1.f / (1.f + __expf(-x0));
                    float z1 = 1.f / (1.f + __expf(-x1));
                    x0 = z0 * e1[ei]     + (1.f - z0) * e2[ei];
                    x1 = z1 * e1[ei + 1] + (1.f - z1) * e2[ei + 1];
                } else if (EPI == EPI_ADD) {
                    size_t ei = (size_t)gr * elds + gc;
                    x0 += e1[ei];
                    x1 += e1[ei + 1];
                }
                if (C) {
                    C[(size_t)gr * ldc + gc]     = x0;
                    C[(size_t)gr * ldc + gc + 1] = x1;
                }
                if (CHi) {
                    size_t o = (size_t)gr * ldcU + (gc >> 1);
                    bf16_split_pair(x0, x1, CHi[o], CLo[o]);
                }
            }
        }
    }

    __syncthreads();
    if (tid == 0) {
        asm volatile("mbarrier.inval.shared.b64 [%0];" :: "r"(barBase) : "memory");
        asm volatile("mbarrier.inval.shared.b64 [%0];" :: "r"(barBase + 8) : "memory");
    }
}

// ---------------------------------------------------------------------------
// scan helpers
// ---------------------------------------------------------------------------
__device__ __forceinline__ void load_a(const float* __restrict__ AL, int d,
                                       float* a, float& a0, bool& structured)
{
    #pragma unroll
    for (int s = 0; s < S_; s++) a[s] = -expf(AL[d * S_ + s]);
    a0 = a[0];
    structured = true;
    #pragma unroll
    for (int s = 0; s < S_; s++) {
        float ideal = (float)(s + 1) * a0;
        if (fabsf(a[s] - ideal) > 1e-4f * fabsf(a[s])) structured = false;
    }
}

__device__ __forceinline__ void make_powers(float q, float* P)
{
    float q2 = q * q, q4 = q2 * q2, q8 = q4 * q4;
    P[0] = q;        P[1] = q2;       P[2] = q2 * q;    P[3] = q4;
    P[4] = q4 * q;   P[5] = q4 * q2;  P[6] = q4 * P[2]; P[7] = q8;
    P[8] = q8 * q;   P[9] = q8 * q2;  P[10]= q8 * P[2]; P[11]= q8 * q4;
    P[12]= q8 * P[4];P[13]= q8 * P[5];P[14]= q8 * P[6]; P[15]= q8 * q8;
}

__device__ __forceinline__ void calc_P(bool structured, float a0, const float* a,
                                       float x, float* P)
{
    if (structured) {
        make_powers(__expf(a0 * x), P);
    } else {
        #pragma unroll
        for (int s = 0; s < 16; s++) P[s] = __expf(a[s] * x);
    }
}

__global__ void __launch_bounds__(128)
scan_partial(const float* __restrict__ Alogf, const float* __restrict__ Alogb)
{
    const int bx  = blockIdx.x;
    const int db  = bx & 3;
    const int c   = bx >> 2;
    const int d   = db * 128 + threadIdx.x;
    const int b   = blockIdx.y;
    const int dir = blockIdx.z;

    float a[S_], a0; bool structured;
    load_a(dir ? Alogb : Alogf, d, a, a0, structured);

    float h[S_];
    #pragma unroll
    for (int s = 0; s < S_; s++) h[s] = 0.f;
    float dts = 0.f;

    for (int t = c * CH_; t < c * CH_ + CH_; t++) {
        const int tt = dir ? (T_ - 1 - t) : t;
        const size_t rb = (size_t)b * T_ + tt;
        const float dtv = g_dtcat[rb * 1024 + dir * 512 + d];
        const float u   = g_enc[rb * D_ + d];
        const float du  = dtv * u;
        dts += dtv;

        const float4* v4 = reinterpret_cast<const float4*>(g_xz + rb * 128 + dir * 64 + 32);
        float4 B0 = v4[0], B1 = v4[1], B2 = v4[2], B3 = v4[3];
        float bc[16] = {B0.x,B0.y,B0.z,B0.w, B1.x,B1.y,B1.z,B1.w,
                        B2.x,B2.y,B2.z,B2.w, B3.x,B3.y,B3.z,B3.w};

        float P[16];
        calc_P(structured, a0, a, dtv, P);

        #pragma unroll
        for (int s = 0; s < 16; s++) h[s] = fmaf(P[s], h[s], du * bc[s]);
    }

    const size_t base = (size_t)(dir * NC_ + c) * B_ + b;
    g_dts[base * D_ + d] = dts;
    #pragma unroll
    for (int s = 0; s < S_; s++)
        g_hfin[(base * S_ + s) * D_ + d] = h[s];
}

__global__ void __launch_bounds__(256)
scan_combine(const float* __restrict__ Alogf, const float* __restrict__ Alogb)
{
    const int idx = blockIdx.x * 256 + threadIdx.x;
    const int dir = idx >> 13;
    const int b   = (idx >> 9) & 15;
    const int d   = idx & 511;

    float a[S_], a0; bool structured;
    load_a(dir ? Alogb : Alogf, d, a, a0, structured);

    float h[S_];
    #pragma unroll
    for (int s = 0; s < S_; s++) h[s] = 0.f;

    for (int c = 0; c < NC_; c++) {
        const size_t base = (size_t)(dir * NC_ + c) * B_ + b;
        #pragma unroll
        for (int s = 0; s < S_; s++)
            g_h0[(base * S_ + s) * D_ + d] = h[s];
        const float dts = g_dts[base * D_ + d];
        float P[16];
        calc_P(structured, a0, a, dts, P);
        #pragma unroll
        for (int s = 0; s < S_; s++)
            h[s] = fmaf(P[s], h[s], g_hfin[(base * S_ + s) * D_ + d]);
    }
}

__global__ void __launch_bounds__(128)
scan_final(const float* __restrict__ Alogf, const float* __restrict__ Alogb,
           const float* __restrict__ Dskf,  const float* __restrict__ Dskb)
{
    const int bx  = blockIdx.x;
    const int db  = bx & 3;
    const int c   = bx >> 2;
    const int d   = db * 128 + threadIdx.x;
    const int b   = blockIdx.y;
    const int dir = blockIdx.z;

    float a[S_], a0; bool structured;
    load_a(dir ? Alogb : Alogf, d, a, a0, structured);
    const float Dsk = (dir ? Dskb : Dskf)[d];

    const size_t base = (size_t)(dir * NC_ + c) * B_ + b;
    float h[S_];
    #pragma unroll
    for (int s = 0; s < S_; s++)
        h[s] = g_h0[(base * S_ + s) * D_ + d];

    for (int t = c * CH_; t < c * CH_ + CH_; t++) {
        const int tt = dir ? (T_ - 1 - t) : t;
        const size_t rb = (size_t)b * T_ + tt;
        const float dtv = g_dtcat[rb * 1024 + dir * 512 + d];
        const float u   = g_enc[rb * D_ + d];
        const float du  = dtv * u;

        const float4* v4 = reinterpret_cast<const float4*>(g_xz + rb * 128 + dir * 64 + 32);
        float4 B0 = v4[0], B1 = v4[1], B2 = v4[2], B3 = v4[3];
        float4 C0 = v4[4], C1 = v4[5], C2 = v4[6], C3 = v4[7];
        float bc[16] = {B0.x,B0.y,B0.z,B0.w, B1.x,B1.y,B1.z,B1.w,
                        B2.x,B2.y,B2.z,B2.w, B3.x,B3.y,B3.z,B3.w};
        float cc[16] = {C0.x,C0.y,C0.z,C0.w, C1.x,C1.y,C1.z,C1.w,
                        C2.x,C2.y,C2.z,C2.w, C3.x,C3.y,C3.z,C3.w};

        float P[16];
        calc_P(structured, a0, a, dtv, P);

        float acc0 = 0.f, acc1 = 0.f, acc2 = 0.f, acc3 = 0.f;
        #pragma unroll
        for (int s = 0; s < 16; s += 4) {
            h[s+0] = fmaf(P[s+0], h[s+0], du * bc[s+0]);
            h[s+1] = fmaf(P[s+1], h[s+1], du * bc[s+1]);
            h[s+2] = fmaf(P[s+2], h[s+2], du * bc[s+2]);
            h[s+3] = fmaf(P[s+3], h[s+3], du * bc[s+3]);
            acc0 = fmaf(h[s+0], cc[s+0], acc0);
            acc1 = fmaf(h[s+1], cc[s+1], acc1);
            acc2 = fmaf(h[s+2], cc[s+2], acc2);
            acc3 = fmaf(h[s+3], cc[s+3], acc3);
        }
        float y = (acc0 + acc1) + (acc2 + acc3) + u * Dsk;
        g_ycat[rb * 1024 + dir * 512 + d] = y;

        float ynb = __shfl_xor_sync(0xffffffffu, y, 1);
        if ((threadIdx.x & 1) == 0) {
            size_t o = rb * 512 + ((dir * 512 + d) >> 1);
            bf16_split_pair(y, ynb, g_ycatH[o], g_ycatL[o]);
        }
    }
}

// ---------------------------------------------------------------------------
// LayerNorm -> hn planes
// ---------------------------------------------------------------------------
__global__ void ln_kernel(const float* __restrict__ gamma, const float* __restrict__ beta)
{
    __shared__ float r1[256];
    __shared__ float r2[256];
    __shared__ float mu_s, rs_s;
    const int row = blockIdx.x;
    const int tid = threadIdx.x;
    const float2 vv = reinterpret_cast<const float2*>(g_hbuf + (size_t)row * D_)[tid];
    r1[tid] = vv.x + vv.y;
    r2[tid] = vv.x * vv.x + vv.y * vv.y;
    __syncthreads();
    for (int off = 128; off > 0; off >>= 1) {
        if (tid < off) { r1[tid] += r1[tid + off]; r2[tid] += r2[tid + off]; }
        __syncthreads();
    }
    if (tid == 0) {
        float mu  = r1[0] / (float)D_;
        float var = r2[0] / (float)D_ - mu * mu;
        mu_s = mu;
        rs_s = rsqrtf(var + 1e-5f);
    }
    __syncthreads();
    float mu = mu_s, rs = rs_s;
    float o0 = (vv.x - mu) * rs * gamma[2 * tid]     + beta[2 * tid];
    float o1 = (vv.y - mu) * rs * gamma[2 * tid + 1] + beta[2 * tid + 1];
    size_t o = (size_t)row * 256 + tid;
    bf16_split_pair(o0, o1, g_hnH[o], g_hnL[o]);
}

// ---------------------------------------------------------------------------
// output
// ---------------------------------------------------------------------------
__global__ void out_kernel(float* __restrict__ out)
{
    int idx = blockIdx.x * 256 + threadIdx.x;
    if (idx >= B_ * PRED_ * N_) return;
    int n = idx % N_;
    int p = (idx / N_) % PRED_;
    int b = idx / (N_ * PRED_);
    float v = g_pre[((size_t)b * T_ + n) * PRED_ + p];
    out[idx] = v * g_std[b * N_ + n] + g_mean[b * N_ + n];
}

// ---------------------------------------------------------------------------
// host: tensor-map construction via driver entry point (no -lcuda needed)
// ---------------------------------------------------------------------------
typedef CUresult (CUDAAPI *PFN_tmEncode)(
    CUtensorMap*, CUtensorMapDataType, cuuint32_t, void*,
    const cuuint64_t*, const cuuint64_t*, const cuuint32_t*, const cuuint32_t*,
    CUtensorMapInterleave, CUtensorMapSwizzle, CUtensorMapL2promotion,
    CUtensorMapFloatOOBfill);

static PFN_tmEncode get_encoder()
{
    void* fn = nullptr;
    cudaDriverEntryPointQueryResult st;
#if CUDART_VERSION >= 12050
    cudaGetDriverEntryPointByVersion("cuTensorMapEncodeTiled", &fn, 12000,
                                     cudaEnableDefault, &st);
#else
    cudaGetDriverEntryPoint("cuTensorMapEncodeTiled", &fn, cudaEnableDefault, &st);
#endif
    return (PFN_tmEncode)fn;
}

static void mk_map(PFN_tmEncode enc, CUtensorMap* m, uint32_t* base,
                   int ldU, int rows, int boxRows)
{
    cuuint64_t dims[2]    = {(cuuint64_t)ldU, (cuuint64_t)rows};
    cuuint64_t strides[1] = {(cuuint64_t)ldU * 4};
    cuuint32_t box[2]     = {32u, (cuuint32_t)boxRows};
    cuuint32_t estr[2]    = {1u, 1u};
    enc(m, CU_TENSOR_MAP_DATA_TYPE_UINT32, 2, (void*)base,
        dims, strides, box, estr,
        CU_TENSOR_MAP_INTERLEAVE_NONE, CU_TENSOR_MAP_SWIZZLE_128B,
        CU_TENSOR_MAP_L2_PROMOTION_L2_128B, CU_TENSOR_MAP_FLOAT_OOB_FILL_NONE);
}

// ---------------------------------------------------------------------------
// launch
// ---------------------------------------------------------------------------
extern "C" void kernel_launch(void* const* d_in, const int* in_sizes, int n_in,
                              void* d_out, int out_size)
{
    const float* x_enc  = (const float*)d_in[0];
    const float* x_mark = (const float*)d_in[1];
    const float* W_emb  = (const float*)d_in[4];
    const float* b_emb  = (const float*)d_in[5];
    const float* Alogf  = (const float*)d_in[6];
    const float* Wx_f   = (const float*)d_in[7];
    const float* Wdt_f  = (const float*)d_in[8];
    const float* bdt_f  = (const float*)d_in[9];
    const float* Dsk_f  = (const float*)d_in[10];
    const float* Alogb  = (const float*)d_in[11];
    const float* Wx_b   = (const float*)d_in[12];
    const float* Wdt_b  = (const float*)d_in[13];
    const float* bdt_b  = (const float*)d_in[14];
    const float* Dsk_b  = (const float*)d_in[15];
    const float* Wz     = (const float*)d_in[16];
    const float* bz     = (const float*)d_in[17];
    const float* Wo     = (const float*)d_in[18];
    const float* bo     = (const float*)d_in[19];
    const float* lng    = (const float*)d_in[20];
    const float* lnb    = (const float*)d_in[21];
    const float* Wproj  = (const float*)d_in[22];
    const float* bproj  = (const float*)d_in[23];
    float* out = (float*)d_out;

    float *enc, *xz, *dtc, *ycat, *hb, *pre, *bdt;
    uint32_t *tokH,*tokL,*encH,*encL,*xzH,*xzL,*ycatH,*ycatL,*fusH,*fusL,*hnH,*hnL;
    uint32_t *wembH,*wembL,*wxH,*wxL,*wdtH,*wdtL,*wzH,*wzL,*woH,*woL,*wpjH,*wpjL;
    cudaGetSymbolAddress((void**)&enc,   g_enc);
    cudaGetSymbolAddress((void**)&xz,    g_xz);
    cudaGetSymbolAddress((void**)&dtc,   g_dtcat);
    cudaGetSymbolAddress((void**)&ycat,  g_ycat);
    cudaGetSymbolAddress((void**)&hb,    g_hbuf);
    cudaGetSymbolAddress((void**)&pre,   g_pre);
    cudaGetSymbolAddress((void**)&bdt,   g_bdt);
    cudaGetSymbolAddress((void**)&tokH,  g_tokH);  cudaGetSymbolAddress((void**)&tokL,  g_tokL);
    cudaGetSymbolAddress((void**)&encH,  g_encH);  cudaGetSymbolAddress((void**)&encL,  g_encL);
    cudaGetSymbolAddress((void**)&xzH,   g_xzH);   cudaGetSymbolAddress((void**)&xzL,   g_xzL);
    cudaGetSymbolAddress((void**)&ycatH, g_ycatH); cudaGetSymbolAddress((void**)&ycatL, g_ycatL);
    cudaGetSymbolAddress((void**)&fusH,  g_fusH);  cudaGetSymbolAddress((void**)&fusL,  g_fusL);
    cudaGetSymbolAddress((void**)&hnH,   g_hnH);   cudaGetSymbolAddress((void**)&hnL,   g_hnL);
    cudaGetSymbolAddress((void**)&wembH, g_wembH); cudaGetSymbolAddress((void**)&wembL, g_wembL);
    cudaGetSymbolAddress((void**)&wxH,   g_wxH);   cudaGetSymbolAddress((void**)&wxL,   g_wxL);
    cudaGetSymbolAddress((void**)&wdtH,  g_wdtH);  cudaGetSymbolAddress((void**)&wdtL,  g_wdtL);
    cudaGetSymbolAddress((void**)&wzH,   g_wzH);   cudaGetSymbolAddress((void**)&wzL,   g_wzL);
    cudaGetSymbolAddress((void**)&woH,   g_woH);   cudaGetSymbolAddress((void**)&woL,   g_woL);
    cudaGetSymbolAddress((void**)&wpjH,  g_wpjH);  cudaGetSymbolAddress((void**)&wpjL,  g_wpjL);

    PFN_tmEncode tm = get_encoder();
    CUtensorMap mTokH, mTokL, mEncH, mEncL, mXzH, mXzL, mYcH, mYcL, mFuH, mFuL, mHnH, mHnL;
    CUtensorMap mWeH, mWeL, mWxH, mWxL, mWdH, mWdL, mWzH, mWzL, mWoH, mWoL, mWpH, mWpL;
    mk_map(tm, &mTokH, tokH, 256, MROWS, 64);  mk_map(tm, &mTokL, tokL, 256, MROWS, 64);
    mk_map(tm, &mEncH, encH, 256, MROWS, 64);  mk_map(tm, &mEncL, encL, 256, MROWS, 64);
    mk_map(tm, &mXzH,  xzH,  64,  MROWS, 64);  mk_map(tm, &mXzL,  xzL,  64,  MROWS, 64);
    mk_map(tm, &mYcH,  ycatH,512, MROWS, 64);  mk_map(tm, &mYcL,  ycatL,512, MROWS, 64);
    mk_map(tm, &mFuH,  fusH, 256, MROWS, 64);  mk_map(tm, &mFuL,  fusL, 256, MROWS, 64);
    mk_map(tm, &mHnH,  hnH,  256, MROWS, 64);  mk_map(tm, &mHnL,  hnL,  256, MROWS, 64);
    mk_map(tm, &mWeH,  wembH,256, 512, 128);   mk_map(tm, &mWeL,  wembL,256, 512, 128);
    mk_map(tm, &mWxH,  wxH,  256, 128, 128);   mk_map(tm, &mWxL,  wxL,  256, 128, 128);
    mk_map(tm, &mWdH,  wdtH, 64,  1024,128);   mk_map(tm, &mWdL,  wdtL, 64,  1024,128);
    mk_map(tm, &mWzH,  wzH,  512, 512, 128);   mk_map(tm, &mWzL,  wzL,  512, 512, 128);
    mk_map(tm, &mWoH,  woH,  256, 512, 128);   mk_map(tm, &mWoL,  woL,  256, 512, 128);
    mk_map(tm, &mWpH,  wpjH, 256, 96,  128);   mk_map(tm, &mWpL,  wpjL, 256, 96,  128);

    cudaFuncSetAttribute(gemm_tma<EPI_NONE>,     cudaFuncAttributeMaxDynamicSharedMemorySize, GEMM_SMEM);
    cudaFuncSetAttribute(gemm_tma<EPI_SOFTPLUS>, cudaFuncAttributeMaxDynamicSharedMemorySize, GEMM_SMEM);
    cudaFuncSetAttribute(gemm_tma<EPI_SIGFUSE>,  cudaFuncAttributeMaxDynamicSharedMemorySize, GEMM_SMEM);
    cudaFuncSetAttribute(gemm_tma<EPI_ADD>,      cudaFuncAttributeMaxDynamicSharedMemorySize, GEMM_SMEM);

    const int gy = (MROWS + 63) / 64;   // 82

    // 0) weight pre-split
    split_weights<<<(I_ALL + 255) / 256, 256>>>(
        W_emb, Wx_f, Wx_b, Wdt_f, Wdt_b, Wz, Wo, Wproj, bdt_f, bdt_b);

    // 1) stats
    stats_kernel<<<dim3(B_, (N_ + 31) / 32), 256>>>(x_enc);

    // 2) tok planes
    build_tok<<<dim3((T_ + 31) / 32, L_ / 32, B_), dim3(32, 8)>>>(x_enc, x_mark);

    // 3) enc = tok @ W_emb + b_emb
    gemm_tma<EPI_NONE><<<dim3(D_ / 128, gy), 256, GEMM_SMEM>>>(
        mTokH, mTokL, mWeH, mWeL, enc, D_, encH, encL, 256,
        MROWS, D_, 512, b_emb, nullptr, nullptr, 0);

    // 4) xz = enc @ [Wx_f|Wx_b]
    gemm_tma<EPI_NONE><<<dim3(1, gy), 256, GEMM_SMEM>>>(
        mEncH, mEncL, mWxH, mWxL, xz, 128, xzH, xzL, 64,
        MROWS, 128, 512, nullptr, nullptr, nullptr, 0);

    // 5) dtcat = softplus(xz @ Wdt_blockdiag + bdt)
    gemm_tma<EPI_SOFTPLUS><<<dim3(8, gy), 256, GEMM_SMEM>>>(
        mXzH, mXzL, mWdH, mWdL, dtc, 1024, nullptr, nullptr, 0,
        MROWS, 1024, 128, bdt, nullptr, nullptr, 0);

    // 6) chunked bidirectional scan
    scan_partial<<<dim3(4 * NC_, B_, 2), 128>>>(Alogf, Alogb);
    scan_combine<<<64, 256>>>(Alogf, Alogb);
    scan_final  <<<dim3(4 * NC_, B_, 2), 128>>>(Alogf, Alogb, Dsk_f, Dsk_b);

    // 7) fused = sigmoid(ycat @ Wz + bz) gate
    gemm_tma<EPI_SIGFUSE><<<dim3(D_ / 128, gy), 256, GEMM_SMEM>>>(
        mYcH, mYcL, mWzH, mWzL, nullptr, 0, fusH, fusL, 256,
        MROWS, D_, 1024, bz, ycat, ycat + D_, 2 * D_);

    // 8) h = enc + fused @ Wo + bo
    gemm_tma<EPI_ADD><<<dim3(D_ / 128, gy), 256, GEMM_SMEM>>>(
        mFuH, mFuL, mWoH, mWoL, hb, D_, nullptr, nullptr, 0,
        MROWS, D_, 512, bo, enc, nullptr, D_);

    // 9) layernorm -> hn planes
    ln_kernel<<<MROWS, 256>>>(lng, lnb);

    // 10) pre = hn @ W_proj + b_proj
    gemm_tma<EPI_NONE><<<dim3(1, gy), 256, GEMM_SMEM>>>(
        mHnH, mHnL, mWpH, mWpL, pre, PRED_, nullptr, nullptr, 0,
        MROWS, PRED_, 512, bproj, nullptr, nullptr, 0);

    // 11) output
    out_kernel<<<(B_ * PRED_ * N_ + 255) / 256, 256>>>(out);
}